// round 2
// baseline (speedup 1.0000x reference)
#include <cuda_runtime.h>
#include <cuda_bf16.h>
#include <math.h>

// ---------------- problem constants ----------------
#define T_    2048
#define D_    2048
#define NQ_   16
#define NKV_  4
#define H_    128
#define E_    16
#define F_    1024
#define TOPK_ 4
#define EPS_  1e-6f
#define SCALE_ 0.088388347648318447f  // 128^-0.5

#define BM 64
#define BN 64
#define BK 16

// ---------------- scratch (device globals; no allocation allowed) ----------------
__device__ float g_hnorm [(size_t)T_ * D_];                 // 16MB
__device__ float g_q     [(size_t)T_ * NQ_ * H_];           // 16MB
__device__ float g_k     [(size_t)T_ * NKV_ * H_];           // 4MB
__device__ float g_v     [(size_t)T_ * NKV_ * H_];           // 4MB
__device__ float g_attnout[(size_t)T_ * NQ_ * H_];          // 16MB
__device__ float g_hres  [(size_t)T_ * D_];                 // 16MB
__device__ float g_h2    [(size_t)T_ * D_];                 // 16MB
__device__ float g_gated [(size_t)T_ * TOPK_ * F_];         // 32MB
__device__ float g_pairout[(size_t)T_ * TOPK_ * D_];        // 64MB

__device__ int   g_topidx[T_ * TOPK_];
__device__ float g_topw  [T_ * TOPK_];
__device__ int   g_counts[E_];
__device__ int   g_offsets[E_];
__device__ int   g_cursor[E_];
__device__ int   g_pair_token[T_ * TOPK_];
__device__ int   g_pair_slot [T_ * TOPK_];

// ---------------- generic fp32 tiled GEMM body (NN) ----------------
__device__ __forceinline__ void gemm_nn_body(
    const float* __restrict__ A, int lda,
    const float* __restrict__ B, int ldb,
    float* __restrict__ C, int ldc,
    int K, const float* __restrict__ resid, int mlimit)
{
    __shared__ float As[BK][BM + 1];
    __shared__ float Bs[BK][BN + 1];
    const int m0 = blockIdx.y * BM;
    const int n0 = blockIdx.x * BN;
    const int tid = threadIdx.x;
    const int tx4 = (tid & 15) * 4;
    const int ty4 = (tid >> 4) * 4;
    float acc[4][4] = {};

    const int idx4 = tid * 4;
    const int am = idx4 >> 4;
    const int ak = idx4 & 15;
    int ar = m0 + am; if (ar >= mlimit) ar = mlimit - 1;

    for (int k0 = 0; k0 < K; k0 += BK) {
        float4 av = *reinterpret_cast<const float4*>(&A[(size_t)ar * lda + k0 + ak]);
        As[ak + 0][am] = av.x; As[ak + 1][am] = av.y;
        As[ak + 2][am] = av.z; As[ak + 3][am] = av.w;
        #pragma unroll
        for (int i = 0; i < 4; i++) {
            int idx = tid + 256 * i;
            int bk = idx >> 6, bn = idx & 63;
            Bs[bk][bn] = B[(size_t)(k0 + bk) * ldb + n0 + bn];
        }
        __syncthreads();
        #pragma unroll
        for (int kk = 0; kk < BK; kk++) {
            float a[4], b[4];
            #pragma unroll
            for (int i = 0; i < 4; i++) a[i] = As[kk][ty4 + i];
            #pragma unroll
            for (int j = 0; j < 4; j++) b[j] = Bs[kk][tx4 + j];
            #pragma unroll
            for (int i = 0; i < 4; i++)
                #pragma unroll
                for (int j = 0; j < 4; j++)
                    acc[i][j] = fmaf(a[i], b[j], acc[i][j]);
        }
        __syncthreads();
    }
    #pragma unroll
    for (int i = 0; i < 4; i++) {
        int m = m0 + ty4 + i;
        if (m >= mlimit) continue;
        #pragma unroll
        for (int j = 0; j < 4; j++) {
            int n = n0 + tx4 + j;
            float v = acc[i][j];
            if (resid) v += resid[(size_t)m * ldc + n];
            C[(size_t)m * ldc + n] = v;
        }
    }
}

// ---------------- kernels ----------------

__global__ void k_rmsnorm(const float* __restrict__ x_ext,
                          const float* __restrict__ w, int mode)
{
    const int t = blockIdx.x;
    const float* px = (mode == 0) ? (x_ext + (size_t)t * D_) : (g_hres + (size_t)t * D_);
    float* py = (mode == 0) ? (g_hnorm + (size_t)t * D_) : (g_h2 + (size_t)t * D_);
    float ss = 0.f;
    for (int d = threadIdx.x; d < D_; d += 256) { float v = px[d]; ss += v * v; }
    __shared__ float red[256];
    red[threadIdx.x] = ss; __syncthreads();
    for (int s = 128; s > 0; s >>= 1) {
        if (threadIdx.x < s) red[threadIdx.x] += red[threadIdx.x + s];
        __syncthreads();
    }
    float r = rsqrtf(red[0] / D_ + EPS_);
    for (int d = threadIdx.x; d < D_; d += 256) py[d] = px[d] * r * w[d];
}

__global__ void __launch_bounds__(256) k_proj(const float* __restrict__ W, int which)
{
    float* C = (which == 0) ? g_q : (which == 1 ? g_k : g_v);
    int n = (which == 0) ? (NQ_ * H_) : (NKV_ * H_);
    gemm_nn_body(g_hnorm, D_, W, n, C, n, D_, nullptr, T_);
}

// per-head RMSNorm + RoPE (rot_dim == H == 128)
__global__ void k_normrope(const float* __restrict__ w,
                           const float* __restrict__ cs,
                           const float* __restrict__ sn, int which)
{
    const int t = blockIdx.x, n = blockIdx.y, d = threadIdx.x; // 128 threads
    float* base = (which == 0) ? g_q : g_k;
    int nh = (which == 0) ? NQ_ : NKV_;
    float* p = base + (size_t)t * nh * H_ + (size_t)n * H_;
    float v = p[d];
    __shared__ float sh[128];
    sh[d] = v * v; __syncthreads();
    for (int s = 64; s > 0; s >>= 1) {
        if (d < s) sh[d] += sh[d + s];
        __syncthreads();
    }
    float r = rsqrtf(sh[0] / H_ + EPS_);
    __syncthreads();
    float xn = v * r * w[d];
    sh[d] = xn; __syncthreads();
    float rot = (d < 64) ? -sh[d + 64] : sh[d - 64];
    p[d] = xn * cs[(size_t)t * H_ + d] + rot * sn[(size_t)t * H_ + d];
}

// ---------------- fused flash attention ----------------
// One block = (64 query rows) x (1 head). Online softmax over causal KV tiles.
// Dynamic smem: Qs[64][129] | KVs[64][129] | Ps[64][65]
#define QS_LD 129
#define PS_LD 65
#define SMEM_FA ((2 * 64 * QS_LD + 64 * PS_LD) * 4)

__global__ void __launch_bounds__(256) k_flashattn()
{
    extern __shared__ float sm[];
    float* Qs  = sm;
    float* KVs = sm + 64 * QS_LD;
    float* Ps  = sm + 2 * 64 * QS_LD;

    const int by = blockIdx.x;     // q tile (32)
    const int n  = blockIdx.y;     // head (16)
    const int kv = n >> 2;
    const int tid = threadIdx.x;
    const int ty = tid >> 4, tx = tid & 15;
    const int ty4 = ty * 4, tx4 = tx * 4, tx8 = tx * 8;
    const int m0 = by * 64;

    // load Q tile (64 x 128)
    #pragma unroll
    for (int i = 0; i < 8; i++) {
        int idx = tid + 256 * i;          // 2048 float4s
        int r = idx >> 5, c4 = (idx & 31) * 4;
        float4 v = *reinterpret_cast<const float4*>(
            &g_q[((size_t)(m0 + r) * NQ_ + n) * H_ + c4]);
        Qs[r * QS_LD + c4 + 0] = v.x; Qs[r * QS_LD + c4 + 1] = v.y;
        Qs[r * QS_LD + c4 + 2] = v.z; Qs[r * QS_LD + c4 + 3] = v.w;
    }

    float m_run[4], l_run[4], o[4][8];
    #pragma unroll
    for (int i = 0; i < 4; i++) {
        m_run[i] = -1e30f; l_run[i] = 0.f;
        #pragma unroll
        for (int j = 0; j < 8; j++) o[i][j] = 0.f;
    }
    __syncthreads();

    for (int kt = 0; kt <= by; kt++) {
        const int s0 = kt * 64;
        // load K tile
        #pragma unroll
        for (int i = 0; i < 8; i++) {
            int idx = tid + 256 * i;
            int r = idx >> 5, c4 = (idx & 31) * 4;
            float4 v = *reinterpret_cast<const float4*>(
                &g_k[((size_t)(s0 + r) * NKV_ + kv) * H_ + c4]);
            KVs[r * QS_LD + c4 + 0] = v.x; KVs[r * QS_LD + c4 + 1] = v.y;
            KVs[r * QS_LD + c4 + 2] = v.z; KVs[r * QS_LD + c4 + 3] = v.w;
        }
        __syncthreads();

        // S = Q K^T (4x4 per thread)
        float s[4][4] = {};
        #pragma unroll 4
        for (int h = 0; h < H_; h++) {
            float a[4], b[4];
            #pragma unroll
            for (int i = 0; i < 4; i++) a[i] = Qs[(ty4 + i) * QS_LD + h];
            #pragma unroll
            for (int j = 0; j < 4; j++) b[j] = KVs[(tx4 + j) * QS_LD + h];
            #pragma unroll
            for (int i = 0; i < 4; i++)
                #pragma unroll
                for (int j = 0; j < 4; j++)
                    s[i][j] = fmaf(a[i], b[j], s[i][j]);
        }
        #pragma unroll
        for (int i = 0; i < 4; i++)
            #pragma unroll
            for (int j = 0; j < 4; j++) {
                s[i][j] *= SCALE_;
                if (kt == by && (tx4 + j) > (ty4 + i)) s[i][j] = -1e30f;
            }

        // online softmax update
        float m_new[4], fac[4], lloc[4];
        #pragma unroll
        for (int i = 0; i < 4; i++) {
            float mx = fmaxf(fmaxf(s[i][0], s[i][1]), fmaxf(s[i][2], s[i][3]));
            #pragma unroll
            for (int w = 1; w < 16; w <<= 1)
                mx = fmaxf(mx, __shfl_xor_sync(0xffffffffu, mx, w));
            m_new[i] = fmaxf(m_run[i], mx);
            fac[i] = __expf(m_run[i] - m_new[i]);
            float ls = 0.f;
            #pragma unroll
            for (int j = 0; j < 4; j++) {
                s[i][j] = __expf(s[i][j] - m_new[i]);
                ls += s[i][j];
            }
            #pragma unroll
            for (int w = 1; w < 16; w <<= 1)
                ls += __shfl_xor_sync(0xffffffffu, ls, w);
            lloc[i] = ls;
        }
        #pragma unroll
        for (int i = 0; i < 4; i++) {
            m_run[i] = m_new[i];
            l_run[i] = l_run[i] * fac[i] + lloc[i];
            #pragma unroll
            for (int j = 0; j < 8; j++) o[i][j] *= fac[i];
            #pragma unroll
            for (int j = 0; j < 4; j++) Ps[(ty4 + i) * PS_LD + tx4 + j] = s[i][j];
        }
        __syncthreads();

        // overwrite KVs with V tile
        #pragma unroll
        for (int i = 0; i < 8; i++) {
            int idx = tid + 256 * i;
            int r = idx >> 5, c4 = (idx & 31) * 4;
            float4 v = *reinterpret_cast<const float4*>(
                &g_v[((size_t)(s0 + r) * NKV_ + kv) * H_ + c4]);
            KVs[r * QS_LD + c4 + 0] = v.x; KVs[r * QS_LD + c4 + 1] = v.y;
            KVs[r * QS_LD + c4 + 2] = v.z; KVs[r * QS_LD + c4 + 3] = v.w;
        }
        __syncthreads();

        // O += P V
        #pragma unroll 2
        for (int k = 0; k < 64; k++) {
            float p[4], vv[8];
            #pragma unroll
            for (int i = 0; i < 4; i++) p[i] = Ps[(ty4 + i) * PS_LD + k];
            #pragma unroll
            for (int j = 0; j < 8; j++) vv[j] = KVs[k * QS_LD + tx8 + j];
            #pragma unroll
            for (int i = 0; i < 4; i++)
                #pragma unroll
                for (int j = 0; j < 8; j++)
                    o[i][j] = fmaf(p[i], vv[j], o[i][j]);
        }
        __syncthreads();
    }

    // write out
    #pragma unroll
    for (int i = 0; i < 4; i++) {
        float inv = 1.f / l_run[i];
        float* dst = &g_attnout[((size_t)(m0 + ty4 + i) * NQ_ + n) * H_ + tx8];
        #pragma unroll
        for (int j = 0; j < 8; j++) dst[j] = o[i][j] * inv;
    }
}

// O projection + residual
__global__ void __launch_bounds__(256) k_oproj(const float* __restrict__ W,
                                               const float* __restrict__ resid)
{
    gemm_nn_body(g_attnout, NQ_ * H_, W, D_, g_hres, D_, NQ_ * H_, resid, T_);
}

__global__ void k_zero()
{
    if (threadIdx.x < E_) g_counts[threadIdx.x] = 0;
}

__global__ void k_router(const float* __restrict__ gate_w)
{
    const int t = blockIdx.x, tid = threadIdx.x; // 128 threads
    const float* x = g_h2 + (size_t)t * D_;
    float acc[E_];
    #pragma unroll
    for (int e = 0; e < E_; e++) acc[e] = 0.f;
    for (int d = tid; d < D_; d += 128) {
        float xv = x[d];
        const float* gw = gate_w + (size_t)d * E_;
        #pragma unroll
        for (int e = 0; e < E_; e++) acc[e] = fmaf(xv, gw[e], acc[e]);
    }
    __shared__ float sh[128 * E_];
    #pragma unroll
    for (int e = 0; e < E_; e++) sh[tid * E_ + e] = acc[e];
    __syncthreads();
    for (int s = 64; s > 0; s >>= 1) {
        if (tid < s)
            #pragma unroll
            for (int e = 0; e < E_; e++) sh[tid * E_ + e] += sh[(tid + s) * E_ + e];
        __syncthreads();
    }
    if (tid == 0) {
        float p[E_];
        float m = -1e30f;
        for (int e = 0; e < E_; e++) m = fmaxf(m, sh[e]);
        float sum = 0.f;
        for (int e = 0; e < E_; e++) { p[e] = __expf(sh[e] - m); sum += p[e]; }
        float invs = 1.f / sum;
        for (int e = 0; e < E_; e++) p[e] *= invs;
        int idx[TOPK_]; float wv[TOPK_]; float wsum = 0.f;
        for (int k = 0; k < TOPK_; k++) {
            int best = 0; float bv = p[0];
            for (int e = 1; e < E_; e++) if (p[e] > bv) { bv = p[e]; best = e; }
            idx[k] = best; wv[k] = bv; wsum += bv; p[best] = -1.f;
        }
        float invw = 1.f / wsum;
        for (int k = 0; k < TOPK_; k++) {
            g_topidx[t * TOPK_ + k] = idx[k];
            g_topw[t * TOPK_ + k] = wv[k] * invw;
            atomicAdd(&g_counts[idx[k]], 1);
        }
    }
}

__global__ void k_scan()
{
    int off = 0;
    for (int e = 0; e < E_; e++) {
        g_offsets[e] = off;
        off += g_counts[e];
        g_cursor[e] = 0;
    }
}

__global__ void k_assign()
{
    int i = blockIdx.x * blockDim.x + threadIdx.x;
    if (i >= T_ * TOPK_) return;
    int e = g_topidx[i];
    int slot = g_offsets[e] + atomicAdd(&g_cursor[e], 1);
    g_pair_token[slot] = i >> 2;
    g_pair_slot[i] = slot;
}

__global__ void __launch_bounds__(256) k_gateup(const float* __restrict__ gate_up_w)
{
    const int e = blockIdx.z;
    const int cnt = g_counts[e];
    const int m0 = blockIdx.y * BM;
    if (m0 >= cnt) return;
    const int base = g_offsets[e];
    const int n0 = blockIdx.x * BN;
    const float* B = gate_up_w + (size_t)e * D_ * (2 * F_);
    __shared__ float As[BK][BM + 1];
    __shared__ float Bg[BK][BN + 1];
    __shared__ float Bu[BK][BN + 1];
    __shared__ int rowTok[BM];
    const int tid = threadIdx.x;
    const int tx4 = (tid & 15) * 4, ty4 = (tid >> 4) * 4;
    if (tid < BM) {
        int r = m0 + tid;
        rowTok[tid] = (r < cnt) ? g_pair_token[base + r] : g_pair_token[base];
    }
    __syncthreads();
    float ag[4][4] = {}, au[4][4] = {};
    const int idx4 = tid * 4;
    const int am = idx4 >> 4, ak = idx4 & 15;
    const int tok = rowTok[am];
    for (int k0 = 0; k0 < D_; k0 += BK) {
        float4 av = *reinterpret_cast<const float4*>(&g_h2[(size_t)tok * D_ + k0 + ak]);
        As[ak + 0][am] = av.x; As[ak + 1][am] = av.y;
        As[ak + 2][am] = av.z; As[ak + 3][am] = av.w;
        #pragma unroll
        for (int i = 0; i < 4; i++) {
            int idx = tid + 256 * i;
            int bk = idx >> 6, bn = idx & 63;
            const float* brow = B + (size_t)(k0 + bk) * (2 * F_);
            Bg[bk][bn] = brow[n0 + bn];
            Bu[bk][bn] = brow[F_ + n0 + bn];
        }
        __syncthreads();
        #pragma unroll
        for (int kk = 0; kk < BK; kk++) {
            float a[4], bg[4], bu[4];
            #pragma unroll
            for (int i = 0; i < 4; i++) a[i] = As[kk][ty4 + i];
            #pragma unroll
            for (int j = 0; j < 4; j++) { bg[j] = Bg[kk][tx4 + j]; bu[j] = Bu[kk][tx4 + j]; }
            #pragma unroll
            for (int i = 0; i < 4; i++)
                #pragma unroll
                for (int j = 0; j < 4; j++) {
                    ag[i][j] = fmaf(a[i], bg[j], ag[i][j]);
                    au[i][j] = fmaf(a[i], bu[j], au[i][j]);
                }
        }
        __syncthreads();
    }
    #pragma unroll
    for (int i = 0; i < 4; i++) {
        int r = m0 + ty4 + i;
        if (r >= cnt) continue;
        #pragma unroll
        for (int j = 0; j < 4; j++) {
            float g = ag[i][j], u = au[i][j];
            float silu = g / (1.f + __expf(-g));
            g_gated[(size_t)(base + r) * F_ + n0 + tx4 + j] = u * silu;
        }
    }
}

__global__ void __launch_bounds__(256) k_down(const float* __restrict__ down_w)
{
    const int e = blockIdx.z;
    const int cnt = g_counts[e];
    if ((int)blockIdx.y * BM >= cnt) return;
    const int base = g_offsets[e];
    gemm_nn_body(g_gated + (size_t)base * F_, F_,
                 down_w + (size_t)e * F_ * D_, D_,
                 g_pairout + (size_t)base * D_, D_,
                 F_, nullptr, cnt);
}

__global__ void k_combine(float* __restrict__ out)
{
    const int t = blockIdx.x;
    const int s0 = g_pair_slot[t * 4 + 0], s1 = g_pair_slot[t * 4 + 1];
    const int s2 = g_pair_slot[t * 4 + 2], s3 = g_pair_slot[t * 4 + 3];
    const float w0 = g_topw[t * 4 + 0], w1 = g_topw[t * 4 + 1];
    const float w2 = g_topw[t * 4 + 2], w3 = g_topw[t * 4 + 3];
    const float* p0 = g_pairout + (size_t)s0 * D_;
    const float* p1 = g_pairout + (size_t)s1 * D_;
    const float* p2 = g_pairout + (size_t)s2 * D_;
    const float* p3 = g_pairout + (size_t)s3 * D_;
    const float* hr = g_hres + (size_t)t * D_;
    float* o = out + (size_t)t * D_;
    for (int d = threadIdx.x; d < D_; d += 256)
        o[d] = hr[d] + w0 * p0[d] + w1 * p1[d] + w2 * p2[d] + w3 * p3[d];
}

// ---------------- launch ----------------
extern "C" void kernel_launch(void* const* d_in, const int* in_sizes, int n_in,
                              void* d_out, int out_size)
{
    const float* hidden = (const float*)d_in[0];
    const float* cosp   = (const float*)d_in[1];
    const float* sinp   = (const float*)d_in[2];
    const float* mask   = (const float*)d_in[3];  (void)mask;
    const float* iln    = (const float*)d_in[4];
    const float* pln    = (const float*)d_in[5];
    const float* qw     = (const float*)d_in[6];
    const float* kw     = (const float*)d_in[7];
    const float* vw     = (const float*)d_in[8];
    const float* ow     = (const float*)d_in[9];
    const float* qnw    = (const float*)d_in[10];
    const float* knw    = (const float*)d_in[11];
    const float* gw     = (const float*)d_in[12];
    const float* guw    = (const float*)d_in[13];
    const float* dw     = (const float*)d_in[14];
    float* out = (float*)d_out;

    static bool attr_set = false;
    if (!attr_set) {
        cudaFuncSetAttribute(k_flashattn,
                             cudaFuncAttributeMaxDynamicSharedMemorySize, SMEM_FA);
        attr_set = true;
    }

    k_rmsnorm<<<T_, 256>>>(hidden, iln, 0);
    k_proj<<<dim3(NQ_ * H_ / BN, T_ / BM), 256>>>(qw, 0);
    k_proj<<<dim3(NKV_ * H_ / BN, T_ / BM), 256>>>(kw, 1);
    k_proj<<<dim3(NKV_ * H_ / BN, T_ / BM), 256>>>(vw, 2);
    k_normrope<<<dim3(T_, NQ_), 128>>>(qnw, cosp, sinp, 0);
    k_normrope<<<dim3(T_, NKV_), 128>>>(knw, cosp, sinp, 1);
    k_flashattn<<<dim3(T_ / 64, NQ_), 256, SMEM_FA>>>();
    k_oproj<<<dim3(D_ / BN, T_ / BM), 256>>>(ow, hidden);
    k_rmsnorm<<<T_, 256>>>(nullptr, pln, 1);
    k_zero<<<1, 32>>>();
    k_router<<<T_, 128>>>(gw);
    k_scan<<<1, 1>>>();
    k_assign<<<(T_ * TOPK_ + 255) / 256, 256>>>();
    k_gateup<<<dim3(F_ / BN, T_ / BM, E_), 256>>>(guw);
    k_down<<<dim3(D_ / BN, T_ / BM, E_), 256>>>(dw);
    k_combine<<<T_, 256>>>(out);
}

// round 4
// speedup vs baseline: 1.8482x; 1.8482x over previous
#include <cuda_runtime.h>
#include <cuda_bf16.h>
#include <math.h>

// ---------------- problem constants ----------------
#define T_    2048
#define D_    2048
#define NQ_   16
#define NKV_  4
#define H_    128
#define E_    16
#define F_    1024
#define TOPK_ 4
#define EPS_  1e-6f
#define SCALE_ 0.088388347648318447f  // 128^-0.5

// ---------------- scratch (device globals; no allocation allowed) ----------------
__device__ float g_hnorm [(size_t)T_ * D_];
__device__ float g_q     [(size_t)T_ * NQ_ * H_];
__device__ float g_k     [(size_t)T_ * NKV_ * H_];
__device__ float g_v     [(size_t)T_ * NKV_ * H_];
__device__ float g_attnout[(size_t)T_ * NQ_ * H_];
__device__ float g_hres  [(size_t)T_ * D_];
__device__ float g_h2    [(size_t)T_ * D_];
__device__ float g_gated [(size_t)T_ * TOPK_ * F_];
__device__ float g_pairout[(size_t)T_ * TOPK_ * D_];

__device__ int   g_topidx[T_ * TOPK_];
__device__ float g_topw  [T_ * TOPK_];
__device__ int   g_counts[E_];
__device__ int   g_offsets[E_];
__device__ int   g_cursor[E_];
__device__ int   g_pair_token[T_ * TOPK_];
__device__ int   g_pair_slot [T_ * TOPK_];

// ---------------- tf32 mma helpers ----------------
__device__ __forceinline__ unsigned f2tf(float x) {
    unsigned u;
    asm("cvt.rna.tf32.f32 %0, %1;" : "=r"(u) : "f"(x));
    return u;
}
__device__ __forceinline__ void mma_tf32(float* d, const unsigned* a, const unsigned* b) {
    asm volatile(
        "mma.sync.aligned.m16n8k8.row.col.f32.tf32.tf32.f32 "
        "{%0,%1,%2,%3},{%4,%5,%6,%7},{%8,%9},{%0,%1,%2,%3};\n"
        : "+f"(d[0]), "+f"(d[1]), "+f"(d[2]), "+f"(d[3])
        : "r"(a[0]), "r"(a[1]), "r"(a[2]), "r"(a[3]), "r"(b[0]), "r"(b[1]));
}

// ---------------- generic tf32 tensor-core GEMM (NN) ----------------
// Tile 128x128, BK=16, 256 threads (8 warps as 2x4). C = A@B (+resid).
__device__ __forceinline__ void gemm_tf32_body(
    const float* __restrict__ A, int lda,
    const float* __restrict__ B, int ldb,
    float* __restrict__ C, int ldc,
    int K, const float* __restrict__ resid, int mlimit)
{
    __shared__ unsigned As[128][17];
    __shared__ unsigned Bs[16][132];
    const int m0 = blockIdx.y * 128, n0 = blockIdx.x * 128;
    const int tid = threadIdx.x, lane = tid & 31, warp = tid >> 5;
    const int wm = warp >> 2, wn = warp & 3;
    const int gid = lane >> 2, tq = lane & 3;
    float acc[4][4][4] = {};

    for (int k0 = 0; k0 < K; k0 += 16) {
        #pragma unroll
        for (int i = 0; i < 2; i++) {
            int idx = tid + 256 * i;
            int r = idx >> 2, c4 = (idx & 3) * 4;
            int ar = m0 + r; if (ar >= mlimit) ar = mlimit - 1;
            float4 v = *reinterpret_cast<const float4*>(&A[(size_t)ar * lda + k0 + c4]);
            As[r][c4 + 0] = f2tf(v.x); As[r][c4 + 1] = f2tf(v.y);
            As[r][c4 + 2] = f2tf(v.z); As[r][c4 + 3] = f2tf(v.w);
        }
        #pragma unroll
        for (int i = 0; i < 2; i++) {
            int idx = tid + 256 * i;
            int r = idx >> 5, c4 = (idx & 31) * 4;
            float4 v = *reinterpret_cast<const float4*>(&B[(size_t)(k0 + r) * ldb + n0 + c4]);
            Bs[r][c4 + 0] = f2tf(v.x); Bs[r][c4 + 1] = f2tf(v.y);
            Bs[r][c4 + 2] = f2tf(v.z); Bs[r][c4 + 3] = f2tf(v.w);
        }
        __syncthreads();
        #pragma unroll
        for (int ks = 0; ks < 16; ks += 8) {
            unsigned a[4][4], b[4][2];
            #pragma unroll
            for (int tm = 0; tm < 4; tm++) {
                int r0 = wm * 64 + tm * 16 + gid;
                a[tm][0] = As[r0][ks + tq];     a[tm][1] = As[r0 + 8][ks + tq];
                a[tm][2] = As[r0][ks + tq + 4]; a[tm][3] = As[r0 + 8][ks + tq + 4];
            }
            #pragma unroll
            for (int tn = 0; tn < 4; tn++) {
                int c = wn * 32 + tn * 8 + gid;
                b[tn][0] = Bs[ks + tq][c]; b[tn][1] = Bs[ks + tq + 4][c];
            }
            #pragma unroll
            for (int tm = 0; tm < 4; tm++)
                #pragma unroll
                for (int tn = 0; tn < 4; tn++)
                    mma_tf32(acc[tm][tn], a[tm], b[tn]);
        }
        __syncthreads();
    }
    #pragma unroll
    for (int tm = 0; tm < 4; tm++) {
        int r0 = m0 + wm * 64 + tm * 16 + gid;
        int r1 = r0 + 8;
        #pragma unroll
        for (int tn = 0; tn < 4; tn++) {
            int c0 = n0 + wn * 32 + tn * 8 + 2 * tq;
            if (r0 < mlimit) {
                float v0 = acc[tm][tn][0], v1 = acc[tm][tn][1];
                if (resid) { v0 += resid[(size_t)r0 * ldc + c0]; v1 += resid[(size_t)r0 * ldc + c0 + 1]; }
                C[(size_t)r0 * ldc + c0] = v0; C[(size_t)r0 * ldc + c0 + 1] = v1;
            }
            if (r1 < mlimit) {
                float v2 = acc[tm][tn][2], v3 = acc[tm][tn][3];
                if (resid) { v2 += resid[(size_t)r1 * ldc + c0]; v3 += resid[(size_t)r1 * ldc + c0 + 1]; }
                C[(size_t)r1 * ldc + c0] = v2; C[(size_t)r1 * ldc + c0 + 1] = v3;
            }
        }
    }
}

// ---------------- kernels ----------------

__global__ void k_rmsnorm(const float* __restrict__ x_ext,
                          const float* __restrict__ w, int mode)
{
    const int t = blockIdx.x;
    const float* px = (mode == 0) ? (x_ext + (size_t)t * D_) : (g_hres + (size_t)t * D_);
    float* py = (mode == 0) ? (g_hnorm + (size_t)t * D_) : (g_h2 + (size_t)t * D_);
    float ss = 0.f;
    for (int d = threadIdx.x; d < D_; d += 256) { float v = px[d]; ss += v * v; }
    __shared__ float red[256];
    red[threadIdx.x] = ss; __syncthreads();
    for (int s = 128; s > 0; s >>= 1) {
        if (threadIdx.x < s) red[threadIdx.x] += red[threadIdx.x + s];
        __syncthreads();
    }
    float r = rsqrtf(red[0] / D_ + EPS_);
    for (int d = threadIdx.x; d < D_; d += 256) py[d] = px[d] * r * w[d];
}

__global__ void __launch_bounds__(256) k_proj(const float* __restrict__ W, int which)
{
    float* C = (which == 0) ? g_q : (which == 1 ? g_k : g_v);
    int n = (which == 0) ? (NQ_ * H_) : (NKV_ * H_);
    gemm_tf32_body(g_hnorm, D_, W, n, C, n, D_, nullptr, T_);
}

__global__ void k_normrope(const float* __restrict__ w,
                           const float* __restrict__ cs,
                           const float* __restrict__ sn, int which)
{
    const int t = blockIdx.x, n = blockIdx.y, d = threadIdx.x; // 128 threads
    float* base = (which == 0) ? g_q : g_k;
    int nh = (which == 0) ? NQ_ : NKV_;
    float* p = base + (size_t)t * nh * H_ + (size_t)n * H_;
    float v = p[d];
    __shared__ float sh[128];
    sh[d] = v * v; __syncthreads();
    for (int s = 64; s > 0; s >>= 1) {
        if (d < s) sh[d] += sh[d + s];
        __syncthreads();
    }
    float r = rsqrtf(sh[0] / H_ + EPS_);
    __syncthreads();
    float xn = v * r * w[d];
    sh[d] = xn; __syncthreads();
    float rot = (d < 64) ? -sh[d + 64] : sh[d - 64];
    p[d] = xn * cs[(size_t)t * H_ + d] + rot * sn[(size_t)t * H_ + d];
}

// ---------------- fused flash attention (scalar fp32) ----------------
#define QS_LD 129
#define PS_LD 65
#define SMEM_FA ((2 * 64 * QS_LD + 64 * PS_LD) * 4)

__global__ void __launch_bounds__(256) k_flashattn()
{
    extern __shared__ float sm[];
    float* Qs  = sm;
    float* KVs = sm + 64 * QS_LD;
    float* Ps  = sm + 2 * 64 * QS_LD;

    const int by = blockIdx.x;
    const int n  = blockIdx.y;
    const int kv = n >> 2;
    const int tid = threadIdx.x;
    const int ty = tid >> 4, tx = tid & 15;
    const int ty4 = ty * 4, tx4 = tx * 4, tx8 = tx * 8;
    const int m0 = by * 64;

    #pragma unroll
    for (int i = 0; i < 8; i++) {
        int idx = tid + 256 * i;
        int r = idx >> 5, c4 = (idx & 31) * 4;
        float4 v = *reinterpret_cast<const float4*>(
            &g_q[((size_t)(m0 + r) * NQ_ + n) * H_ + c4]);
        Qs[r * QS_LD + c4 + 0] = v.x; Qs[r * QS_LD + c4 + 1] = v.y;
        Qs[r * QS_LD + c4 + 2] = v.z; Qs[r * QS_LD + c4 + 3] = v.w;
    }

    float m_run[4], l_run[4], o[4][8];
    #pragma unroll
    for (int i = 0; i < 4; i++) {
        m_run[i] = -1e30f; l_run[i] = 0.f;
        #pragma unroll
        for (int j = 0; j < 8; j++) o[i][j] = 0.f;
    }
    __syncthreads();

    for (int kt = 0; kt <= by; kt++) {
        const int s0 = kt * 64;
        #pragma unroll
        for (int i = 0; i < 8; i++) {
            int idx = tid + 256 * i;
            int r = idx >> 5, c4 = (idx & 31) * 4;
            float4 v = *reinterpret_cast<const float4*>(
                &g_k[((size_t)(s0 + r) * NKV_ + kv) * H_ + c4]);
            KVs[r * QS_LD + c4 + 0] = v.x; KVs[r * QS_LD + c4 + 1] = v.y;
            KVs[r * QS_LD + c4 + 2] = v.z; KVs[r * QS_LD + c4 + 3] = v.w;
        }
        __syncthreads();

        float s[4][4] = {};
        #pragma unroll 4
        for (int h = 0; h < H_; h++) {
            float a[4], b[4];
            #pragma unroll
            for (int i = 0; i < 4; i++) a[i] = Qs[(ty4 + i) * QS_LD + h];
            #pragma unroll
            for (int j = 0; j < 4; j++) b[j] = KVs[(tx4 + j) * QS_LD + h];
            #pragma unroll
            for (int i = 0; i < 4; i++)
                #pragma unroll
                for (int j = 0; j < 4; j++)
                    s[i][j] = fmaf(a[i], b[j], s[i][j]);
        }
        #pragma unroll
        for (int i = 0; i < 4; i++)
            #pragma unroll
            for (int j = 0; j < 4; j++) {
                s[i][j] *= SCALE_;
                if (kt == by && (tx4 + j) > (ty4 + i)) s[i][j] = -1e30f;
            }

        float m_new[4], fac[4], lloc[4];
        #pragma unroll
        for (int i = 0; i < 4; i++) {
            float mx = fmaxf(fmaxf(s[i][0], s[i][1]), fmaxf(s[i][2], s[i][3]));
            #pragma unroll
            for (int w = 1; w < 16; w <<= 1)
                mx = fmaxf(mx, __shfl_xor_sync(0xffffffffu, mx, w));
            m_new[i] = fmaxf(m_run[i], mx);
            fac[i] = __expf(m_run[i] - m_new[i]);
            float ls = 0.f;
            #pragma unroll
            for (int j = 0; j < 4; j++) {
                s[i][j] = __expf(s[i][j] - m_new[i]);
                ls += s[i][j];
            }
            #pragma unroll
            for (int w = 1; w < 16; w <<= 1)
                ls += __shfl_xor_sync(0xffffffffu, ls, w);
            lloc[i] = ls;
        }
        #pragma unroll
        for (int i = 0; i < 4; i++) {
            m_run[i] = m_new[i];
            l_run[i] = l_run[i] * fac[i] + lloc[i];
            #pragma unroll
            for (int j = 0; j < 8; j++) o[i][j] *= fac[i];
            #pragma unroll
            for (int j = 0; j < 4; j++) Ps[(ty4 + i) * PS_LD + tx4 + j] = s[i][j];
        }
        __syncthreads();

        #pragma unroll
        for (int i = 0; i < 8; i++) {
            int idx = tid + 256 * i;
            int r = idx >> 5, c4 = (idx & 31) * 4;
            float4 v = *reinterpret_cast<const float4*>(
                &g_v[((size_t)(s0 + r) * NKV_ + kv) * H_ + c4]);
            KVs[r * QS_LD + c4 + 0] = v.x; KVs[r * QS_LD + c4 + 1] = v.y;
            KVs[r * QS_LD + c4 + 2] = v.z; KVs[r * QS_LD + c4 + 3] = v.w;
        }
        __syncthreads();

        #pragma unroll 2
        for (int k = 0; k < 64; k++) {
            float p[4], vv[8];
            #pragma unroll
            for (int i = 0; i < 4; i++) p[i] = Ps[(ty4 + i) * PS_LD + k];
            #pragma unroll
            for (int j = 0; j < 8; j++) vv[j] = KVs[k * QS_LD + tx8 + j];
            #pragma unroll
            for (int i = 0; i < 4; i++)
                #pragma unroll
                for (int j = 0; j < 8; j++)
                    o[i][j] = fmaf(p[i], vv[j], o[i][j]);
        }
        __syncthreads();
    }

    #pragma unroll
    for (int i = 0; i < 4; i++) {
        float inv = 1.f / l_run[i];
        float* dst = &g_attnout[((size_t)(m0 + ty4 + i) * NQ_ + n) * H_ + tx8];
        #pragma unroll
        for (int j = 0; j < 8; j++) dst[j] = o[i][j] * inv;
    }
}

__global__ void __launch_bounds__(256) k_oproj(const float* __restrict__ W,
                                               const float* __restrict__ resid)
{
    gemm_tf32_body(g_attnout, NQ_ * H_, W, D_, g_hres, D_, NQ_ * H_, resid, T_);
}

__global__ void k_zero()
{
    if (threadIdx.x < E_) g_counts[threadIdx.x] = 0;
}

__global__ void k_router(const float* __restrict__ gate_w)
{
    const int t = blockIdx.x, tid = threadIdx.x; // 128 threads
    const float* x = g_h2 + (size_t)t * D_;
    float acc[E_];
    #pragma unroll
    for (int e = 0; e < E_; e++) acc[e] = 0.f;
    for (int d = tid; d < D_; d += 128) {
        float xv = x[d];
        const float* gw = gate_w + (size_t)d * E_;
        #pragma unroll
        for (int e = 0; e < E_; e++) acc[e] = fmaf(xv, gw[e], acc[e]);
    }
    __shared__ float sh[128 * E_];
    #pragma unroll
    for (int e = 0; e < E_; e++) sh[tid * E_ + e] = acc[e];
    __syncthreads();
    for (int s = 64; s > 0; s >>= 1) {
        if (tid < s)
            #pragma unroll
            for (int e = 0; e < E_; e++) sh[tid * E_ + e] += sh[(tid + s) * E_ + e];
        __syncthreads();
    }
    if (tid == 0) {
        float p[E_];
        float m = -1e30f;
        for (int e = 0; e < E_; e++) m = fmaxf(m, sh[e]);
        float sum = 0.f;
        for (int e = 0; e < E_; e++) { p[e] = __expf(sh[e] - m); sum += p[e]; }
        float invs = 1.f / sum;
        for (int e = 0; e < E_; e++) p[e] *= invs;
        int idx[TOPK_]; float wv[TOPK_]; float wsum = 0.f;
        for (int k = 0; k < TOPK_; k++) {
            int best = 0; float bv = p[0];
            for (int e = 1; e < E_; e++) if (p[e] > bv) { bv = p[e]; best = e; }
            idx[k] = best; wv[k] = bv; wsum += bv; p[best] = -1.f;
        }
        float invw = 1.f / wsum;
        for (int k = 0; k < TOPK_; k++) {
            g_topidx[t * TOPK_ + k] = idx[k];
            g_topw[t * TOPK_ + k] = wv[k] * invw;
            atomicAdd(&g_counts[idx[k]], 1);
        }
    }
}

__global__ void k_scan()
{
    int off = 0;
    for (int e = 0; e < E_; e++) {
        g_offsets[e] = off;
        off += g_counts[e];
        g_cursor[e] = 0;
    }
}

__global__ void k_assign()
{
    int i = blockIdx.x * blockDim.x + threadIdx.x;
    if (i >= T_ * TOPK_) return;
    int e = g_topidx[i];
    int slot = g_offsets[e] + atomicAdd(&g_cursor[e], 1);
    g_pair_token[slot] = i >> 2;
    g_pair_slot[i] = slot;
}

// ---------------- MoE gate_up (tf32 mma, dual-B, SiLU epilogue) ----------------
// Tile: 128 rows x 64 f-cols. 8 warps as 2x4 (warp: 64x16).
__global__ void __launch_bounds__(256) k_gateup(const float* __restrict__ gate_up_w)
{
    const int e = blockIdx.z;
    const int cnt = g_counts[e];
    const int m0 = blockIdx.y * 128;
    if (m0 >= cnt) return;
    const int base = g_offsets[e];
    const int n0 = blockIdx.x * 64;
    const float* B = gate_up_w + (size_t)e * D_ * (2 * F_);

    __shared__ unsigned As[128][17];
    __shared__ unsigned Bg[16][68];
    __shared__ unsigned Bu[16][68];
    __shared__ int rowTok[128];

    const int tid = threadIdx.x, lane = tid & 31, warp = tid >> 5;
    const int wm = warp >> 2, wn = warp & 3;
    const int gid = lane >> 2, tq = lane & 3;

    if (tid < 128) {
        int r = m0 + tid;
        rowTok[tid] = (r < cnt) ? g_pair_token[base + r] : g_pair_token[base];
    }
    __syncthreads();

    float ag[4][2][4] = {}, au[4][2][4] = {};

    for (int k0 = 0; k0 < D_; k0 += 16) {
        #pragma unroll
        for (int i = 0; i < 2; i++) {
            int idx = tid + 256 * i;
            int r = idx >> 2, c4 = (idx & 3) * 4;
            int tok = rowTok[r];
            float4 v = *reinterpret_cast<const float4*>(&g_h2[(size_t)tok * D_ + k0 + c4]);
            As[r][c4 + 0] = f2tf(v.x); As[r][c4 + 1] = f2tf(v.y);
            As[r][c4 + 2] = f2tf(v.z); As[r][c4 + 3] = f2tf(v.w);
        }
        {
            int r = tid >> 4, c4 = (tid & 15) * 4;
            const float* brow = B + (size_t)(k0 + r) * (2 * F_);
            float4 vg = *reinterpret_cast<const float4*>(&brow[n0 + c4]);
            float4 vu = *reinterpret_cast<const float4*>(&brow[F_ + n0 + c4]);
            Bg[r][c4 + 0] = f2tf(vg.x); Bg[r][c4 + 1] = f2tf(vg.y);
            Bg[r][c4 + 2] = f2tf(vg.z); Bg[r][c4 + 3] = f2tf(vg.w);
            Bu[r][c4 + 0] = f2tf(vu.x); Bu[r][c4 + 1] = f2tf(vu.y);
            Bu[r][c4 + 2] = f2tf(vu.z); Bu[r][c4 + 3] = f2tf(vu.w);
        }
        __syncthreads();
        #pragma unroll
        for (int ks = 0; ks < 16; ks += 8) {
            unsigned a[4][4], bg[2][2], bu[2][2];
            #pragma unroll
            for (int tm = 0; tm < 4; tm++) {
                int r0 = wm * 64 + tm * 16 + gid;
                a[tm][0] = As[r0][ks + tq];     a[tm][1] = As[r0 + 8][ks + tq];
                a[tm][2] = As[r0][ks + tq + 4]; a[tm][3] = As[r0 + 8][ks + tq + 4];
            }
            #pragma unroll
            for (int tn = 0; tn < 2; tn++) {
                int c = wn * 16 + tn * 8 + gid;
                bg[tn][0] = Bg[ks + tq][c]; bg[tn][1] = Bg[ks + tq + 4][c];
                bu[tn][0] = Bu[ks + tq][c]; bu[tn][1] = Bu[ks + tq + 4][c];
            }
            #pragma unroll
            for (int tm = 0; tm < 4; tm++)
                #pragma unroll
                for (int tn = 0; tn < 2; tn++) {
                    mma_tf32(ag[tm][tn], a[tm], bg[tn]);
                    mma_tf32(au[tm][tn], a[tm], bu[tn]);
                }
        }
        __syncthreads();
    }
    #pragma unroll
    for (int tm = 0; tm < 4; tm++) {
        int r0 = m0 + wm * 64 + tm * 16 + gid;
        int r1 = r0 + 8;
        #pragma unroll
        for (int tn = 0; tn < 2; tn++) {
            int c0 = n0 + wn * 16 + tn * 8 + 2 * tq;
            if (r0 < cnt) {
                float g0 = ag[tm][tn][0], u0 = au[tm][tn][0];
                float g1 = ag[tm][tn][1], u1 = au[tm][tn][1];
                g_gated[(size_t)(base + r0) * F_ + c0]     = u0 * (g0 / (1.f + __expf(-g0)));
                g_gated[(size_t)(base + r0) * F_ + c0 + 1] = u1 * (g1 / (1.f + __expf(-g1)));
            }
            if (r1 < cnt) {
                float g2 = ag[tm][tn][2], u2 = au[tm][tn][2];
                float g3 = ag[tm][tn][3], u3 = au[tm][tn][3];
                g_gated[(size_t)(base + r1) * F_ + c0]     = u2 * (g2 / (1.f + __expf(-g2)));
                g_gated[(size_t)(base + r1) * F_ + c0 + 1] = u3 * (g3 / (1.f + __expf(-g3)));
            }
        }
    }
}

__global__ void __launch_bounds__(256) k_down(const float* __restrict__ down_w)
{
    const int e = blockIdx.z;
    const int cnt = g_counts[e];
    if ((int)blockIdx.y * 128 >= cnt) return;
    const int base = g_offsets[e];
    gemm_tf32_body(g_gated + (size_t)base * F_, F_,
                   down_w + (size_t)e * F_ * D_, D_,
                   g_pairout + (size_t)base * D_, D_,
                   F_, nullptr, cnt);
}

__global__ void k_combine(float* __restrict__ out)
{
    const int t = blockIdx.x;
    const int s0 = g_pair_slot[t * 4 + 0], s1 = g_pair_slot[t * 4 + 1];
    const int s2 = g_pair_slot[t * 4 + 2], s3 = g_pair_slot[t * 4 + 3];
    const float w0 = g_topw[t * 4 + 0], w1 = g_topw[t * 4 + 1];
    const float w2 = g_topw[t * 4 + 2], w3 = g_topw[t * 4 + 3];
    const float* p0 = g_pairout + (size_t)s0 * D_;
    const float* p1 = g_pairout + (size_t)s1 * D_;
    const float* p2 = g_pairout + (size_t)s2 * D_;
    const float* p3 = g_pairout + (size_t)s3 * D_;
    const float* hr = g_hres + (size_t)t * D_;
    float* o = out + (size_t)t * D_;
    for (int d = threadIdx.x; d < D_; d += 256)
        o[d] = hr[d] + w0 * p0[d] + w1 * p1[d] + w2 * p2[d] + w3 * p3[d];
}

// ---------------- launch ----------------
extern "C" void kernel_launch(void* const* d_in, const int* in_sizes, int n_in,
                              void* d_out, int out_size)
{
    const float* hidden = (const float*)d_in[0];
    const float* cosp   = (const float*)d_in[1];
    const float* sinp   = (const float*)d_in[2];
    const float* iln    = (const float*)d_in[4];
    const float* pln    = (const float*)d_in[5];
    const float* qw     = (const float*)d_in[6];
    const float* kw     = (const float*)d_in[7];
    const float* vw     = (const float*)d_in[8];
    const float* ow     = (const float*)d_in[9];
    const float* qnw    = (const float*)d_in[10];
    const float* knw    = (const float*)d_in[11];
    const float* gw     = (const float*)d_in[12];
    const float* guw    = (const float*)d_in[13];
    const float* dw     = (const float*)d_in[14];
    float* out = (float*)d_out;

    static bool attr_set = false;
    if (!attr_set) {
        cudaFuncSetAttribute(k_flashattn,
                             cudaFuncAttributeMaxDynamicSharedMemorySize, SMEM_FA);
        attr_set = true;
    }

    k_rmsnorm<<<T_, 256>>>(hidden, iln, 0);
    k_proj<<<dim3(NQ_ * H_ / 128, T_ / 128), 256>>>(qw, 0);
    k_proj<<<dim3(NKV_ * H_ / 128, T_ / 128), 256>>>(kw, 1);
    k_proj<<<dim3(NKV_ * H_ / 128, T_ / 128), 256>>>(vw, 2);
    k_normrope<<<dim3(T_, NQ_), 128>>>(qnw, cosp, sinp, 0);
    k_normrope<<<dim3(T_, NKV_), 128>>>(knw, cosp, sinp, 1);
    k_flashattn<<<dim3(T_ / 64, NQ_), 256, SMEM_FA>>>();
    k_oproj<<<dim3(D_ / 128, T_ / 128), 256>>>(ow, hidden);
    k_rmsnorm<<<T_, 256>>>(nullptr, pln, 1);
    k_zero<<<1, 32>>>();
    k_router<<<T_, 128>>>(gw);
    k_scan<<<1, 1>>>();
    k_assign<<<(T_ * TOPK_ + 255) / 256, 256>>>();
    k_gateup<<<dim3(F_ / 64, T_ * TOPK_ / 128, E_), 256>>>(guw);
    k_down<<<dim3(D_ / 128, T_ * TOPK_ / 128, E_), 256>>>(dw);
    k_combine<<<T_, 256>>>(out);
}

// round 5
// speedup vs baseline: 2.3078x; 1.2487x over previous
#include <cuda_runtime.h>
#include <cuda_bf16.h>
#include <math.h>

// ---------------- problem constants ----------------
#define T_    2048
#define D_    2048
#define NQ_   16
#define NKV_  4
#define H_    128
#define E_    16
#define F_    1024
#define TOPK_ 4
#define EPS_  1e-6f
#define SCALE_ 0.088388347648318447f  // 128^-0.5

// ---------------- scratch (device globals; no allocation allowed) ----------------
__device__ float g_hnorm [(size_t)T_ * D_];
__device__ float g_q     [(size_t)T_ * NQ_ * H_];
__device__ float g_k     [(size_t)T_ * NKV_ * H_];
__device__ float g_v     [(size_t)T_ * NKV_ * H_];
__device__ float g_attnout[(size_t)T_ * NQ_ * H_];
__device__ float g_hres  [(size_t)T_ * D_];
__device__ float g_h2    [(size_t)T_ * D_];
__device__ float g_gated [(size_t)T_ * TOPK_ * F_];
__device__ float g_pairout[(size_t)T_ * TOPK_ * D_];

__device__ int   g_topidx[T_ * TOPK_];
__device__ float g_topw  [T_ * TOPK_];
__device__ int   g_counts[E_];
__device__ int   g_offsets[E_];
__device__ int   g_cursor[E_];
__device__ int   g_pair_token[T_ * TOPK_];
__device__ int   g_pair_slot [T_ * TOPK_];

// ---------------- mma / cp.async helpers ----------------
__device__ __forceinline__ void mma_tf32(float* d, const unsigned* a, const unsigned* b) {
    asm volatile(
        "mma.sync.aligned.m16n8k8.row.col.f32.tf32.tf32.f32 "
        "{%0,%1,%2,%3},{%4,%5,%6,%7},{%8,%9},{%0,%1,%2,%3};\n"
        : "+f"(d[0]), "+f"(d[1]), "+f"(d[2]), "+f"(d[3])
        : "r"(a[0]), "r"(a[1]), "r"(a[2]), "r"(a[3]), "r"(b[0]), "r"(b[1]));
}
__device__ __forceinline__ void cpa16(void* smem, const void* g) {
    unsigned s = (unsigned)__cvta_generic_to_shared(smem);
    asm volatile("cp.async.cg.shared.global [%0], [%1], 16;\n" :: "r"(s), "l"(g));
}
__device__ __forceinline__ void cpa_commit() {
    asm volatile("cp.async.commit_group;\n");
}
__device__ __forceinline__ void cpa_wait0() {
    asm volatile("cp.async.wait_group 0;\n");
}

// ---------------- generic tf32 tensor-core GEMM (NN), cp.async double-buffered ----
// Tile 128x128, BK=16, 256 threads (8 warps as 2x4). C = A@B (+resid).
// A values are consumed as raw f32 bits (tf32 truncation in HW).
#define AS_LD 20
#define BS_LD 136
__device__ __forceinline__ void gemm_tf32_body(
    const float* __restrict__ A, int lda,
    const float* __restrict__ B, int ldb,
    float* __restrict__ C, int ldc,
    int n0, int K, const float* __restrict__ resid, int mlimit)
{
    __shared__ float As[2][128][AS_LD];
    __shared__ float Bs[2][16][BS_LD];
    const int m0 = blockIdx.y * 128;
    const int tid = threadIdx.x, lane = tid & 31, warp = tid >> 5;
    const int wm = warp >> 2, wn = warp & 3;
    const int gid = lane >> 2, tq = lane & 3;
    float acc[4][4][4] = {};

    // A-load indices: 512 float4s over 2 per thread
    const int ar0 = tid >> 1;                 // row 0..127
    const int ac0 = (tid & 1) * 8;            // col 0 or 8 (two float4s below)
    int arow = m0 + ar0; if (arow >= mlimit) arow = mlimit - 1;
    // B-load indices
    const int br0 = tid >> 5;                 // 0..7 (x2)
    const int bc0 = (tid & 31) * 4;

    const int niter = K >> 4;
    // prefetch stage 0
    {
        cpa16(&As[0][ar0][ac0],     &A[(size_t)arow * lda + ac0]);
        cpa16(&As[0][ar0][ac0 + 4], &A[(size_t)arow * lda + ac0 + 4]);
        cpa16(&Bs[0][br0][bc0],     &B[(size_t)br0 * ldb + n0 + bc0]);
        cpa16(&Bs[0][br0 + 8][bc0], &B[(size_t)(br0 + 8) * ldb + n0 + bc0]);
        cpa_commit();
    }
    for (int it = 0; it < niter; it++) {
        cpa_wait0();
        __syncthreads();
        if (it + 1 < niter) {
            int k0 = (it + 1) << 4;
            int nb = (it + 1) & 1;
            cpa16(&As[nb][ar0][ac0],     &A[(size_t)arow * lda + k0 + ac0]);
            cpa16(&As[nb][ar0][ac0 + 4], &A[(size_t)arow * lda + k0 + ac0 + 4]);
            cpa16(&Bs[nb][br0][bc0],     &B[(size_t)(k0 + br0) * ldb + n0 + bc0]);
            cpa16(&Bs[nb][br0 + 8][bc0], &B[(size_t)(k0 + br0 + 8) * ldb + n0 + bc0]);
            cpa_commit();
        }
        const int cb = it & 1;
        #pragma unroll
        for (int ks = 0; ks < 16; ks += 8) {
            unsigned a[4][4], b[4][2];
            #pragma unroll
            for (int tm = 0; tm < 4; tm++) {
                int r0 = wm * 64 + tm * 16 + gid;
                a[tm][0] = __float_as_uint(As[cb][r0][ks + tq]);
                a[tm][1] = __float_as_uint(As[cb][r0 + 8][ks + tq]);
                a[tm][2] = __float_as_uint(As[cb][r0][ks + tq + 4]);
                a[tm][3] = __float_as_uint(As[cb][r0 + 8][ks + tq + 4]);
            }
            #pragma unroll
            for (int tn = 0; tn < 4; tn++) {
                int c = wn * 32 + tn * 8 + gid;
                b[tn][0] = __float_as_uint(Bs[cb][ks + tq][c]);
                b[tn][1] = __float_as_uint(Bs[cb][ks + tq + 4][c]);
            }
            #pragma unroll
            for (int tm = 0; tm < 4; tm++)
                #pragma unroll
                for (int tn = 0; tn < 4; tn++)
                    mma_tf32(acc[tm][tn], a[tm], b[tn]);
        }
        __syncthreads();
    }
    #pragma unroll
    for (int tm = 0; tm < 4; tm++) {
        int r0 = m0 + wm * 64 + tm * 16 + gid;
        int r1 = r0 + 8;
        #pragma unroll
        for (int tn = 0; tn < 4; tn++) {
            int c0 = n0 + wn * 32 + tn * 8 + 2 * tq;
            if (r0 < mlimit) {
                float v0 = acc[tm][tn][0], v1 = acc[tm][tn][1];
                if (resid) { v0 += resid[(size_t)r0 * ldc + c0]; v1 += resid[(size_t)r0 * ldc + c0 + 1]; }
                C[(size_t)r0 * ldc + c0] = v0; C[(size_t)r0 * ldc + c0 + 1] = v1;
            }
            if (r1 < mlimit) {
                float v2 = acc[tm][tn][2], v3 = acc[tm][tn][3];
                if (resid) { v2 += resid[(size_t)r1 * ldc + c0]; v3 += resid[(size_t)r1 * ldc + c0 + 1]; }
                C[(size_t)r1 * ldc + c0] = v2; C[(size_t)r1 * ldc + c0 + 1] = v3;
            }
        }
    }
}

// ---------------- kernels ----------------

__global__ void k_rmsnorm(const float* __restrict__ x_ext,
                          const float* __restrict__ w, int mode)
{
    const int t = blockIdx.x;
    const float* px = (mode == 0) ? (x_ext + (size_t)t * D_) : (g_hres + (size_t)t * D_);
    float* py = (mode == 0) ? (g_hnorm + (size_t)t * D_) : (g_h2 + (size_t)t * D_);
    float ss = 0.f;
    for (int d = threadIdx.x; d < D_; d += 256) { float v = px[d]; ss += v * v; }
    __shared__ float red[256];
    red[threadIdx.x] = ss; __syncthreads();
    for (int s = 128; s > 0; s >>= 1) {
        if (threadIdx.x < s) red[threadIdx.x] += red[threadIdx.x + s];
        __syncthreads();
    }
    float r = rsqrtf(red[0] / D_ + EPS_);
    for (int d = threadIdx.x; d < D_; d += 256) py[d] = px[d] * r * w[d];
}

// fused QKV projection: blockIdx.x 0..15 -> q tile, 16..19 -> k, 20..23 -> v
__global__ void __launch_bounds__(256) k_qkv(const float* __restrict__ qw,
                                             const float* __restrict__ kw,
                                             const float* __restrict__ vw)
{
    const int bx = blockIdx.x;
    if (bx < 16) {
        gemm_tf32_body(g_hnorm, D_, qw, NQ_ * H_, g_q, NQ_ * H_, bx * 128, D_, nullptr, T_);
    } else if (bx < 20) {
        gemm_tf32_body(g_hnorm, D_, kw, NKV_ * H_, g_k, NKV_ * H_, (bx - 16) * 128, D_, nullptr, T_);
    } else {
        gemm_tf32_body(g_hnorm, D_, vw, NKV_ * H_, g_v, NKV_ * H_, (bx - 20) * 128, D_, nullptr, T_);
    }
}

__global__ void k_normrope(const float* __restrict__ w,
                           const float* __restrict__ cs,
                           const float* __restrict__ sn, int which)
{
    const int t = blockIdx.x, n = blockIdx.y, d = threadIdx.x; // 128 threads
    float* base = (which == 0) ? g_q : g_k;
    int nh = (which == 0) ? NQ_ : NKV_;
    float* p = base + (size_t)t * nh * H_ + (size_t)n * H_;
    float v = p[d];
    __shared__ float sh[128];
    sh[d] = v * v; __syncthreads();
    for (int s = 64; s > 0; s >>= 1) {
        if (d < s) sh[d] += sh[d + s];
        __syncthreads();
    }
    float r = rsqrtf(sh[0] / H_ + EPS_);
    __syncthreads();
    float xn = v * r * w[d];
    sh[d] = xn; __syncthreads();
    float rot = (d < 64) ? -sh[d + 64] : sh[d - 64];
    p[d] = xn * cs[(size_t)t * H_ + d] + rot * sn[(size_t)t * H_ + d];
}

// ---------------- fused flash attention (scalar fp32) ----------------
#define QS_LD 129
#define PS_LD 65
#define SMEM_FA ((2 * 64 * QS_LD + 64 * PS_LD) * 4)

__global__ void __launch_bounds__(256) k_flashattn()
{
    extern __shared__ float sm[];
    float* Qs  = sm;
    float* KVs = sm + 64 * QS_LD;
    float* Ps  = sm + 2 * 64 * QS_LD;

    const int by = blockIdx.x;
    const int n  = blockIdx.y;
    const int kv = n >> 2;
    const int tid = threadIdx.x;
    const int ty = tid >> 4, tx = tid & 15;
    const int ty4 = ty * 4, tx4 = tx * 4, tx8 = tx * 8;
    const int m0 = by * 64;

    #pragma unroll
    for (int i = 0; i < 8; i++) {
        int idx = tid + 256 * i;
        int r = idx >> 5, c4 = (idx & 31) * 4;
        float4 v = *reinterpret_cast<const float4*>(
            &g_q[((size_t)(m0 + r) * NQ_ + n) * H_ + c4]);
        Qs[r * QS_LD + c4 + 0] = v.x; Qs[r * QS_LD + c4 + 1] = v.y;
        Qs[r * QS_LD + c4 + 2] = v.z; Qs[r * QS_LD + c4 + 3] = v.w;
    }

    float m_run[4], l_run[4], o[4][8];
    #pragma unroll
    for (int i = 0; i < 4; i++) {
        m_run[i] = -1e30f; l_run[i] = 0.f;
        #pragma unroll
        for (int j = 0; j < 8; j++) o[i][j] = 0.f;
    }
    __syncthreads();

    for (int kt = 0; kt <= by; kt++) {
        const int s0 = kt * 64;
        #pragma unroll
        for (int i = 0; i < 8; i++) {
            int idx = tid + 256 * i;
            int r = idx >> 5, c4 = (idx & 31) * 4;
            float4 v = *reinterpret_cast<const float4*>(
                &g_k[((size_t)(s0 + r) * NKV_ + kv) * H_ + c4]);
            KVs[r * QS_LD + c4 + 0] = v.x; KVs[r * QS_LD + c4 + 1] = v.y;
            KVs[r * QS_LD + c4 + 2] = v.z; KVs[r * QS_LD + c4 + 3] = v.w;
        }
        __syncthreads();

        float s[4][4] = {};
        #pragma unroll 4
        for (int h = 0; h < H_; h++) {
            float a[4], b[4];
            #pragma unroll
            for (int i = 0; i < 4; i++) a[i] = Qs[(ty4 + i) * QS_LD + h];
            #pragma unroll
            for (int j = 0; j < 4; j++) b[j] = KVs[(tx4 + j) * QS_LD + h];
            #pragma unroll
            for (int i = 0; i < 4; i++)
                #pragma unroll
                for (int j = 0; j < 4; j++)
                    s[i][j] = fmaf(a[i], b[j], s[i][j]);
        }
        #pragma unroll
        for (int i = 0; i < 4; i++)
            #pragma unroll
            for (int j = 0; j < 4; j++) {
                s[i][j] *= SCALE_;
                if (kt == by && (tx4 + j) > (ty4 + i)) s[i][j] = -1e30f;
            }

        float m_new[4], fac[4], lloc[4];
        #pragma unroll
        for (int i = 0; i < 4; i++) {
            float mx = fmaxf(fmaxf(s[i][0], s[i][1]), fmaxf(s[i][2], s[i][3]));
            #pragma unroll
            for (int w = 1; w < 16; w <<= 1)
                mx = fmaxf(mx, __shfl_xor_sync(0xffffffffu, mx, w));
            m_new[i] = fmaxf(m_run[i], mx);
            fac[i] = __expf(m_run[i] - m_new[i]);
            float ls = 0.f;
            #pragma unroll
            for (int j = 0; j < 4; j++) {
                s[i][j] = __expf(s[i][j] - m_new[i]);
                ls += s[i][j];
            }
            #pragma unroll
            for (int w = 1; w < 16; w <<= 1)
                ls += __shfl_xor_sync(0xffffffffu, ls, w);
            lloc[i] = ls;
        }
        #pragma unroll
        for (int i = 0; i < 4; i++) {
            m_run[i] = m_new[i];
            l_run[i] = l_run[i] * fac[i] + lloc[i];
            #pragma unroll
            for (int j = 0; j < 8; j++) o[i][j] *= fac[i];
            #pragma unroll
            for (int j = 0; j < 4; j++) Ps[(ty4 + i) * PS_LD + tx4 + j] = s[i][j];
        }
        __syncthreads();

        #pragma unroll
        for (int i = 0; i < 8; i++) {
            int idx = tid + 256 * i;
            int r = idx >> 5, c4 = (idx & 31) * 4;
            float4 v = *reinterpret_cast<const float4*>(
                &g_v[((size_t)(s0 + r) * NKV_ + kv) * H_ + c4]);
            KVs[r * QS_LD + c4 + 0] = v.x; KVs[r * QS_LD + c4 + 1] = v.y;
            KVs[r * QS_LD + c4 + 2] = v.z; KVs[r * QS_LD + c4 + 3] = v.w;
        }
        __syncthreads();

        #pragma unroll 2
        for (int k = 0; k < 64; k++) {
            float p[4], vv[8];
            #pragma unroll
            for (int i = 0; i < 4; i++) p[i] = Ps[(ty4 + i) * PS_LD + k];
            #pragma unroll
            for (int j = 0; j < 8; j++) vv[j] = KVs[k * QS_LD + tx8 + j];
            #pragma unroll
            for (int i = 0; i < 4; i++)
                #pragma unroll
                for (int j = 0; j < 8; j++)
                    o[i][j] = fmaf(p[i], vv[j], o[i][j]);
        }
        __syncthreads();
    }

    #pragma unroll
    for (int i = 0; i < 4; i++) {
        float inv = 1.f / l_run[i];
        float* dst = &g_attnout[((size_t)(m0 + ty4 + i) * NQ_ + n) * H_ + tx8];
        #pragma unroll
        for (int j = 0; j < 8; j++) dst[j] = o[i][j] * inv;
    }
}

__global__ void __launch_bounds__(256) k_oproj(const float* __restrict__ W,
                                               const float* __restrict__ resid)
{
    gemm_tf32_body(g_attnout, NQ_ * H_, W, D_, g_hres, D_,
                   blockIdx.x * 128, NQ_ * H_, resid, T_);
}

__global__ void k_zero()
{
    if (threadIdx.x < E_) g_counts[threadIdx.x] = 0;
}

__global__ void k_router(const float* __restrict__ gate_w)
{
    const int t = blockIdx.x, tid = threadIdx.x; // 128 threads
    const float* x = g_h2 + (size_t)t * D_;
    float acc[E_];
    #pragma unroll
    for (int e = 0; e < E_; e++) acc[e] = 0.f;
    for (int d = tid; d < D_; d += 128) {
        float xv = x[d];
        const float* gw = gate_w + (size_t)d * E_;
        #pragma unroll
        for (int e = 0; e < E_; e++) acc[e] = fmaf(xv, gw[e], acc[e]);
    }
    __shared__ float sh[128 * E_];
    #pragma unroll
    for (int e = 0; e < E_; e++) sh[tid * E_ + e] = acc[e];
    __syncthreads();
    for (int s = 64; s > 0; s >>= 1) {
        if (tid < s)
            #pragma unroll
            for (int e = 0; e < E_; e++) sh[tid * E_ + e] += sh[(tid + s) * E_ + e];
        __syncthreads();
    }
    if (tid == 0) {
        float p[E_];
        float m = -1e30f;
        for (int e = 0; e < E_; e++) m = fmaxf(m, sh[e]);
        float sum = 0.f;
        for (int e = 0; e < E_; e++) { p[e] = __expf(sh[e] - m); sum += p[e]; }
        float invs = 1.f / sum;
        for (int e = 0; e < E_; e++) p[e] *= invs;
        int idx[TOPK_]; float wv[TOPK_]; float wsum = 0.f;
        for (int k = 0; k < TOPK_; k++) {
            int best = 0; float bv = p[0];
            for (int e = 1; e < E_; e++) if (p[e] > bv) { bv = p[e]; best = e; }
            idx[k] = best; wv[k] = bv; wsum += bv; p[best] = -1.f;
        }
        float invw = 1.f / wsum;
        for (int k = 0; k < TOPK_; k++) {
            g_topidx[t * TOPK_ + k] = idx[k];
            g_topw[t * TOPK_ + k] = wv[k] * invw;
            atomicAdd(&g_counts[idx[k]], 1);
        }
    }
}

__global__ void k_scan()
{
    int off = 0;
    for (int e = 0; e < E_; e++) {
        g_offsets[e] = off;
        off += g_counts[e];
        g_cursor[e] = 0;
    }
}

__global__ void k_assign()
{
    int i = blockIdx.x * blockDim.x + threadIdx.x;
    if (i >= T_ * TOPK_) return;
    int e = g_topidx[i];
    int slot = g_offsets[e] + atomicAdd(&g_cursor[e], 1);
    g_pair_token[slot] = i >> 2;
    g_pair_slot[i] = slot;
}

// ---------------- MoE gate_up (tf32 mma, dual-B, SiLU, cp.async double-buffered) --
// Tile: 128 rows x 64 f-cols. 8 warps as 2x4 (warp: 64x16 of each matrix).
#define BGU_LD 72
__global__ void __launch_bounds__(256) k_gateup(const float* __restrict__ gate_up_w)
{
    const int e = blockIdx.z;
    const int cnt = g_counts[e];
    const int m0 = blockIdx.y * 128;
    if (m0 >= cnt) return;
    const int base = g_offsets[e];
    const int n0 = blockIdx.x * 64;
    const float* B = gate_up_w + (size_t)e * D_ * (2 * F_);

    __shared__ float As[2][128][AS_LD];
    __shared__ float Bg[2][16][BGU_LD];
    __shared__ float Bu[2][16][BGU_LD];
    __shared__ int rowTok[128];

    const int tid = threadIdx.x, lane = tid & 31, warp = tid >> 5;
    const int wm = warp >> 2, wn = warp & 3;
    const int gid = lane >> 2, tq = lane & 3;

    if (tid < 128) {
        int r = m0 + tid;
        rowTok[tid] = (r < cnt) ? g_pair_token[base + r] : g_pair_token[base];
    }
    __syncthreads();

    const int ar0 = tid >> 1;
    const int ac0 = (tid & 1) * 8;
    const size_t arow = (size_t)rowTok[ar0] * D_;
    const int br0 = tid >> 4;          // 0..15
    const int bc0 = (tid & 15) * 4;    // 0..60

    float ag[4][2][4] = {}, au[4][2][4] = {};

    {
        cpa16(&As[0][ar0][ac0],     &g_h2[arow + ac0]);
        cpa16(&As[0][ar0][ac0 + 4], &g_h2[arow + ac0 + 4]);
        const float* brow = B + (size_t)br0 * (2 * F_);
        cpa16(&Bg[0][br0][bc0], &brow[n0 + bc0]);
        cpa16(&Bu[0][br0][bc0], &brow[F_ + n0 + bc0]);
        cpa_commit();
    }
    for (int it = 0; it < (D_ >> 4); it++) {
        cpa_wait0();
        __syncthreads();
        if (it + 1 < (D_ >> 4)) {
            int k0 = (it + 1) << 4;
            int nb = (it + 1) & 1;
            cpa16(&As[nb][ar0][ac0],     &g_h2[arow + k0 + ac0]);
            cpa16(&As[nb][ar0][ac0 + 4], &g_h2[arow + k0 + ac0 + 4]);
            const float* brow = B + (size_t)(k0 + br0) * (2 * F_);
            cpa16(&Bg[nb][br0][bc0], &brow[n0 + bc0]);
            cpa16(&Bu[nb][br0][bc0], &brow[F_ + n0 + bc0]);
            cpa_commit();
        }
        const int cb = it & 1;
        #pragma unroll
        for (int ks = 0; ks < 16; ks += 8) {
            unsigned a[4][4], bg[2][2], bu[2][2];
            #pragma unroll
            for (int tm = 0; tm < 4; tm++) {
                int r0 = wm * 64 + tm * 16 + gid;
                a[tm][0] = __float_as_uint(As[cb][r0][ks + tq]);
                a[tm][1] = __float_as_uint(As[cb][r0 + 8][ks + tq]);
                a[tm][2] = __float_as_uint(As[cb][r0][ks + tq + 4]);
                a[tm][3] = __float_as_uint(As[cb][r0 + 8][ks + tq + 4]);
            }
            #pragma unroll
            for (int tn = 0; tn < 2; tn++) {
                int c = wn * 16 + tn * 8 + gid;
                bg[tn][0] = __float_as_uint(Bg[cb][ks + tq][c]);
                bg[tn][1] = __float_as_uint(Bg[cb][ks + tq + 4][c]);
                bu[tn][0] = __float_as_uint(Bu[cb][ks + tq][c]);
                bu[tn][1] = __float_as_uint(Bu[cb][ks + tq + 4][c]);
            }
            #pragma unroll
            for (int tm = 0; tm < 4; tm++)
                #pragma unroll
                for (int tn = 0; tn < 2; tn++) {
                    mma_tf32(ag[tm][tn], a[tm], bg[tn]);
                    mma_tf32(au[tm][tn], a[tm], bu[tn]);
                }
        }
        __syncthreads();
    }
    #pragma unroll
    for (int tm = 0; tm < 4; tm++) {
        int r0 = m0 + wm * 64 + tm * 16 + gid;
        int r1 = r0 + 8;
        #pragma unroll
        for (int tn = 0; tn < 2; tn++) {
            int c0 = n0 + wn * 16 + tn * 8 + 2 * tq;
            if (r0 < cnt) {
                float g0 = ag[tm][tn][0], u0 = au[tm][tn][0];
                float g1 = ag[tm][tn][1], u1 = au[tm][tn][1];
                g_gated[(size_t)(base + r0) * F_ + c0]     = u0 * (g0 / (1.f + __expf(-g0)));
                g_gated[(size_t)(base + r0) * F_ + c0 + 1] = u1 * (g1 / (1.f + __expf(-g1)));
            }
            if (r1 < cnt) {
                float g2 = ag[tm][tn][2], u2 = au[tm][tn][2];
                float g3 = ag[tm][tn][3], u3 = au[tm][tn][3];
                g_gated[(size_t)(base + r1) * F_ + c0]     = u2 * (g2 / (1.f + __expf(-g2)));
                g_gated[(size_t)(base + r1) * F_ + c0 + 1] = u3 * (g3 / (1.f + __expf(-g3)));
            }
        }
    }
}

__global__ void __launch_bounds__(256) k_down(const float* __restrict__ down_w)
{
    const int e = blockIdx.z;
    const int cnt = g_counts[e];
    if ((int)blockIdx.y * 128 >= cnt) return;
    const int base = g_offsets[e];
    gemm_tf32_body(g_gated + (size_t)base * F_, F_,
                   down_w + (size_t)e * F_ * D_, D_,
                   g_pairout + (size_t)base * D_, D_,
                   blockIdx.x * 128, F_, nullptr, cnt);
}

__global__ void k_combine(float* __restrict__ out)
{
    const int t = blockIdx.x;
    const int s0 = g_pair_slot[t * 4 + 0], s1 = g_pair_slot[t * 4 + 1];
    const int s2 = g_pair_slot[t * 4 + 2], s3 = g_pair_slot[t * 4 + 3];
    const float w0 = g_topw[t * 4 + 0], w1 = g_topw[t * 4 + 1];
    const float w2 = g_topw[t * 4 + 2], w3 = g_topw[t * 4 + 3];
    const float* p0 = g_pairout + (size_t)s0 * D_;
    const float* p1 = g_pairout + (size_t)s1 * D_;
    const float* p2 = g_pairout + (size_t)s2 * D_;
    const float* p3 = g_pairout + (size_t)s3 * D_;
    const float* hr = g_hres + (size_t)t * D_;
    float* o = out + (size_t)t * D_;
    for (int d = threadIdx.x; d < D_; d += 256)
        o[d] = hr[d] + w0 * p0[d] + w1 * p1[d] + w2 * p2[d] + w3 * p3[d];
}

// ---------------- launch ----------------
extern "C" void kernel_launch(void* const* d_in, const int* in_sizes, int n_in,
                              void* d_out, int out_size)
{
    const float* hidden = (const float*)d_in[0];
    const float* cosp   = (const float*)d_in[1];
    const float* sinp   = (const float*)d_in[2];
    const float* iln    = (const float*)d_in[4];
    const float* pln    = (const float*)d_in[5];
    const float* qw     = (const float*)d_in[6];
    const float* kw     = (const float*)d_in[7];
    const float* vw     = (const float*)d_in[8];
    const float* ow     = (const float*)d_in[9];
    const float* qnw    = (const float*)d_in[10];
    const float* knw    = (const float*)d_in[11];
    const float* gw     = (const float*)d_in[12];
    const float* guw    = (const float*)d_in[13];
    const float* dw     = (const float*)d_in[14];
    float* out = (float*)d_out;

    static bool attr_set = false;
    if (!attr_set) {
        cudaFuncSetAttribute(k_flashattn,
                             cudaFuncAttributeMaxDynamicSharedMemorySize, SMEM_FA);
        attr_set = true;
    }

    k_rmsnorm<<<T_, 256>>>(hidden, iln, 0);
    k_qkv<<<dim3(24, T_ / 128), 256>>>(qw, kw, vw);
    k_normrope<<<dim3(T_, NQ_), 128>>>(qnw, cosp, sinp, 0);
    k_normrope<<<dim3(T_, NKV_), 128>>>(knw, cosp, sinp, 1);
    k_flashattn<<<dim3(T_ / 64, NQ_), 256, SMEM_FA>>>();
    k_oproj<<<dim3(D_ / 128, T_ / 128), 256>>>(ow, hidden);
    k_rmsnorm<<<T_, 256>>>(nullptr, pln, 1);
    k_zero<<<1, 32>>>();
    k_router<<<T_, 128>>>(gw);
    k_scan<<<1, 1>>>();
    k_assign<<<(T_ * TOPK_ + 255) / 256, 256>>>();
    k_gateup<<<dim3(F_ / 64, T_ * TOPK_ / 128, E_), 256>>>(guw);
    k_down<<<dim3(D_ / 128, T_ * TOPK_ / 128, E_), 256>>>(dw);
    k_combine<<<T_, 256>>>(out);
}

// round 6
// speedup vs baseline: 3.5738x; 1.5486x over previous
#include <cuda_runtime.h>
#include <cuda_bf16.h>
#include <math.h>

// ---------------- problem constants ----------------
#define T_    2048
#define D_    2048
#define NQ_   16
#define NKV_  4
#define H_    128
#define E_    16
#define F_    1024
#define TOPK_ 4
#define EPS_  1e-6f
#define SCALE_ 0.088388347648318447f  // 128^-0.5

// ---------------- scratch (device globals; no allocation allowed) ----------------
__device__ float g_hnorm [(size_t)T_ * D_];
__device__ float g_q     [(size_t)T_ * NQ_ * H_];
__device__ float g_k     [(size_t)T_ * NKV_ * H_];
__device__ float g_v     [(size_t)T_ * NKV_ * H_];
__device__ float g_attnout[(size_t)T_ * NQ_ * H_];
__device__ float g_hres  [(size_t)T_ * D_];
__device__ float g_h2    [(size_t)T_ * D_];
__device__ float g_gated [(size_t)T_ * TOPK_ * F_];
__device__ float g_pairout[(size_t)T_ * TOPK_ * D_];

__device__ int   g_topidx[T_ * TOPK_];
__device__ float g_topw  [T_ * TOPK_];
__device__ int   g_counts[E_];
__device__ int   g_offsets[E_];
__device__ int   g_cursor[E_];
__device__ int   g_pair_token[T_ * TOPK_];
__device__ int   g_pair_slot [T_ * TOPK_];

// ---------------- mma / cp.async helpers ----------------
__device__ __forceinline__ void mma_tf32(float* d, const unsigned* a, const unsigned* b) {
    asm volatile(
        "mma.sync.aligned.m16n8k8.row.col.f32.tf32.tf32.f32 "
        "{%0,%1,%2,%3},{%4,%5,%6,%7},{%8,%9},{%0,%1,%2,%3};\n"
        : "+f"(d[0]), "+f"(d[1]), "+f"(d[2]), "+f"(d[3])
        : "r"(a[0]), "r"(a[1]), "r"(a[2]), "r"(a[3]), "r"(b[0]), "r"(b[1]));
}
__device__ __forceinline__ void cpa16(void* smem, const void* g) {
    unsigned s = (unsigned)__cvta_generic_to_shared(smem);
    asm volatile("cp.async.cg.shared.global [%0], [%1], 16;\n" :: "r"(s), "l"(g));
}
__device__ __forceinline__ void cpa_commit() {
    asm volatile("cp.async.commit_group;\n");
}
__device__ __forceinline__ void cpa_wait0() {
    asm volatile("cp.async.wait_group 0;\n");
}
__device__ __forceinline__ void cpa_wait1() {
    asm volatile("cp.async.wait_group 1;\n");
}

// ---------------- generic tf32 GEMM (NN), 3-stage cp.async pipeline -------------
// Tile 128x128, BK=16, 256 threads (8 warps as 2x4). Dynamic smem.
#define AS_LD 20
#define BS_LD 136
#define GEMM_SMEM ((3 * 128 * AS_LD + 3 * 16 * BS_LD) * 4)
__device__ __forceinline__ void gemm_tf32_body(
    float* dsm,
    const float* __restrict__ A, int lda,
    const float* __restrict__ B, int ldb,
    float* __restrict__ C, int ldc,
    int n0, int K, const float* __restrict__ resid, int mlimit)
{
    float* As = dsm;                        // [3][128][AS_LD]
    float* Bs = dsm + 3 * 128 * AS_LD;      // [3][16][BS_LD]
    const int m0 = blockIdx.y * 128;
    const int tid = threadIdx.x, lane = tid & 31, warp = tid >> 5;
    const int wm = warp >> 2, wn = warp & 3;
    const int gid = lane >> 2, tq = lane & 3;
    float acc[4][4][4] = {};

    const int ar0 = tid >> 1;
    const int ac0 = (tid & 1) * 8;
    int arow = m0 + ar0; if (arow >= mlimit) arow = mlimit - 1;
    const int br0 = tid >> 5;
    const int bc0 = (tid & 31) * 4;

    const int niter = K >> 4;
    auto issue = [&](int it) {
        int k0 = it << 4;
        int st = it % 3;
        float* as = As + st * 128 * AS_LD;
        float* bs = Bs + st * 16 * BS_LD;
        cpa16(&as[ar0 * AS_LD + ac0],     &A[(size_t)arow * lda + k0 + ac0]);
        cpa16(&as[ar0 * AS_LD + ac0 + 4], &A[(size_t)arow * lda + k0 + ac0 + 4]);
        cpa16(&bs[br0 * BS_LD + bc0],       &B[(size_t)(k0 + br0) * ldb + n0 + bc0]);
        cpa16(&bs[(br0 + 8) * BS_LD + bc0], &B[(size_t)(k0 + br0 + 8) * ldb + n0 + bc0]);
        cpa_commit();
    };
    issue(0);
    if (niter > 1) issue(1);

    for (int it = 0; it < niter; it++) {
        if (it + 1 < niter) cpa_wait1(); else cpa_wait0();
        __syncthreads();
        if (it + 2 < niter) issue(it + 2);
        const float* as = As + (it % 3) * 128 * AS_LD;
        const float* bs = Bs + (it % 3) * 16 * BS_LD;
        #pragma unroll
        for (int ks = 0; ks < 16; ks += 8) {
            unsigned a[4][4], b[4][2];
            #pragma unroll
            for (int tm = 0; tm < 4; tm++) {
                int r0 = wm * 64 + tm * 16 + gid;
                a[tm][0] = __float_as_uint(as[r0 * AS_LD + ks + tq]);
                a[tm][1] = __float_as_uint(as[(r0 + 8) * AS_LD + ks + tq]);
                a[tm][2] = __float_as_uint(as[r0 * AS_LD + ks + tq + 4]);
                a[tm][3] = __float_as_uint(as[(r0 + 8) * AS_LD + ks + tq + 4]);
            }
            #pragma unroll
            for (int tn = 0; tn < 4; tn++) {
                int c = wn * 32 + tn * 8 + gid;
                b[tn][0] = __float_as_uint(bs[(ks + tq) * BS_LD + c]);
                b[tn][1] = __float_as_uint(bs[(ks + tq + 4) * BS_LD + c]);
            }
            #pragma unroll
            for (int tm = 0; tm < 4; tm++)
                #pragma unroll
                for (int tn = 0; tn < 4; tn++)
                    mma_tf32(acc[tm][tn], a[tm], b[tn]);
        }
        __syncthreads();
    }
    #pragma unroll
    for (int tm = 0; tm < 4; tm++) {
        int r0 = m0 + wm * 64 + tm * 16 + gid;
        int r1 = r0 + 8;
        #pragma unroll
        for (int tn = 0; tn < 4; tn++) {
            int c0 = n0 + wn * 32 + tn * 8 + 2 * tq;
            if (r0 < mlimit) {
                float v0 = acc[tm][tn][0], v1 = acc[tm][tn][1];
                if (resid) { v0 += resid[(size_t)r0 * ldc + c0]; v1 += resid[(size_t)r0 * ldc + c0 + 1]; }
                C[(size_t)r0 * ldc + c0] = v0; C[(size_t)r0 * ldc + c0 + 1] = v1;
            }
            if (r1 < mlimit) {
                float v2 = acc[tm][tn][2], v3 = acc[tm][tn][3];
                if (resid) { v2 += resid[(size_t)r1 * ldc + c0]; v3 += resid[(size_t)r1 * ldc + c0 + 1]; }
                C[(size_t)r1 * ldc + c0] = v2; C[(size_t)r1 * ldc + c0 + 1] = v3;
            }
        }
    }
}

// ---------------- kernels ----------------

__global__ void k_rmsnorm(const float* __restrict__ x_ext,
                          const float* __restrict__ w, int mode)
{
    const int t = blockIdx.x;
    const float* px = (mode == 0) ? (x_ext + (size_t)t * D_) : (g_hres + (size_t)t * D_);
    float* py = (mode == 0) ? (g_hnorm + (size_t)t * D_) : (g_h2 + (size_t)t * D_);
    float ss = 0.f;
    for (int d = threadIdx.x; d < D_; d += 256) { float v = px[d]; ss += v * v; }
    __shared__ float red[256];
    red[threadIdx.x] = ss; __syncthreads();
    for (int s = 128; s > 0; s >>= 1) {
        if (threadIdx.x < s) red[threadIdx.x] += red[threadIdx.x + s];
        __syncthreads();
    }
    float r = rsqrtf(red[0] / D_ + EPS_);
    for (int d = threadIdx.x; d < D_; d += 256) py[d] = px[d] * r * w[d];
}

// fused QKV projection: blockIdx.x 0..15 -> q tile, 16..19 -> k, 20..23 -> v
__global__ void __launch_bounds__(256) k_qkv(const float* __restrict__ qw,
                                             const float* __restrict__ kw,
                                             const float* __restrict__ vw)
{
    extern __shared__ float dsm[];
    const int bx = blockIdx.x;
    if (bx < 16) {
        gemm_tf32_body(dsm, g_hnorm, D_, qw, NQ_ * H_, g_q, NQ_ * H_, bx * 128, D_, nullptr, T_);
    } else if (bx < 20) {
        gemm_tf32_body(dsm, g_hnorm, D_, kw, NKV_ * H_, g_k, NKV_ * H_, (bx - 16) * 128, D_, nullptr, T_);
    } else {
        gemm_tf32_body(dsm, g_hnorm, D_, vw, NKV_ * H_, g_v, NKV_ * H_, (bx - 20) * 128, D_, nullptr, T_);
    }
}

__global__ void k_normrope(const float* __restrict__ w,
                           const float* __restrict__ cs,
                           const float* __restrict__ sn, int which)
{
    const int t = blockIdx.x, n = blockIdx.y, d = threadIdx.x; // 128 threads
    float* base = (which == 0) ? g_q : g_k;
    int nh = (which == 0) ? NQ_ : NKV_;
    float* p = base + (size_t)t * nh * H_ + (size_t)n * H_;
    float v = p[d];
    __shared__ float sh[128];
    sh[d] = v * v; __syncthreads();
    for (int s = 64; s > 0; s >>= 1) {
        if (d < s) sh[d] += sh[d + s];
        __syncthreads();
    }
    float r = rsqrtf(sh[0] / H_ + EPS_);
    __syncthreads();
    float xn = v * r * w[d];
    sh[d] = xn; __syncthreads();
    float rot = (d < 64) ? -sh[d + 64] : sh[d - 64];
    p[d] = xn * cs[(size_t)t * H_ + d] + rot * sn[(size_t)t * H_ + d];
}

// ---------------- flash attention with tf32 mma ----------------
// Block: 64 q-rows x 1 head. 8 warps as 4(m) x 2(n). Online softmax via SMEM stats.
#define FKV_LD 132
#define FPS_LD 68
#define FA_SMEM ((64 * FKV_LD + 2 * 64 * FKV_LD + 2 * 64 * FKV_LD + 64 * FPS_LD + 3 * 64) * 4)

__global__ void __launch_bounds__(256) k_flashattn()
{
    extern __shared__ float sm[];
    float* Qs    = sm;                          // 64 x FKV_LD
    float* Ks    = Qs + 64 * FKV_LD;            // 2 x 64 x FKV_LD
    float* Vs    = Ks + 2 * 64 * FKV_LD;        // 2 x 64 x FKV_LD
    float* Ps    = Vs + 2 * 64 * FKV_LD;        // 64 x FPS_LD
    float* m_s   = Ps + 64 * FPS_LD;
    float* l_s   = m_s + 64;
    float* fac_s = l_s + 64;

    const int by = blockIdx.x;      // q tile
    const int n  = blockIdx.y;      // head
    const int kv = n >> 2;
    const int tid = threadIdx.x, lane = tid & 31, warp = tid >> 5;
    const int wm = warp >> 1, wn = warp & 1;
    const int gid = lane >> 2, tq = lane & 3;
    const int m0 = by * 64;

    // Q tile via cp.async
    #pragma unroll
    for (int i = 0; i < 8; i++) {
        int idx = tid + 256 * i;
        int r = idx >> 5, c4 = (idx & 31) * 4;
        cpa16(&Qs[r * FKV_LD + c4], &g_q[((size_t)(m0 + r) * NQ_ + n) * H_ + c4]);
    }
    if (tid < 64) { m_s[tid] = -1e30f; l_s[tid] = 0.f; }

    auto issue_kv = [&](int kt, int buf) {
        int s0 = kt * 64;
        float* kd = Ks + buf * 64 * FKV_LD;
        float* vd = Vs + buf * 64 * FKV_LD;
        #pragma unroll
        for (int i = 0; i < 8; i++) {
            int idx = tid + 256 * i;
            int r = idx >> 5, c4 = (idx & 31) * 4;
            cpa16(&kd[r * FKV_LD + c4], &g_k[((size_t)(s0 + r) * NKV_ + kv) * H_ + c4]);
            cpa16(&vd[r * FKV_LD + c4], &g_v[((size_t)(s0 + r) * NKV_ + kv) * H_ + c4]);
        }
        cpa_commit();
    };
    issue_kv(0, 0);

    float o[8][4] = {};

    for (int kt = 0; kt <= by; kt++) {
        cpa_wait0();
        __syncthreads();
        if (kt < by) issue_kv(kt + 1, (kt + 1) & 1);

        const float* K = Ks + (kt & 1) * 64 * FKV_LD;
        const float* V = Vs + (kt & 1) * 64 * FKV_LD;
        const int s0 = kt * 64;

        // ---- S = Q K^T (tf32 mma), warp tile m16 x n32 ----
        float s[4][4] = {};
        #pragma unroll
        for (int ks = 0; ks < H_; ks += 8) {
            unsigned a[4], b[4][2];
            int r0 = wm * 16 + gid;
            a[0] = __float_as_uint(Qs[r0 * FKV_LD + ks + tq]);
            a[1] = __float_as_uint(Qs[(r0 + 8) * FKV_LD + ks + tq]);
            a[2] = __float_as_uint(Qs[r0 * FKV_LD + ks + tq + 4]);
            a[3] = __float_as_uint(Qs[(r0 + 8) * FKV_LD + ks + tq + 4]);
            #pragma unroll
            for (int f = 0; f < 4; f++) {
                int c = wn * 32 + f * 8 + gid;
                b[f][0] = __float_as_uint(K[c * FKV_LD + ks + tq]);
                b[f][1] = __float_as_uint(K[c * FKV_LD + ks + tq + 4]);
            }
            #pragma unroll
            for (int f = 0; f < 4; f++) mma_tf32(s[f], a, b[f]);
        }
        // scale + causal mask -> Ps
        {
            int r0 = wm * 16 + gid;
            #pragma unroll
            for (int f = 0; f < 4; f++) {
                int c = wn * 32 + f * 8 + 2 * tq;
                float v0 = s[f][0] * SCALE_, v1 = s[f][1] * SCALE_;
                float v2 = s[f][2] * SCALE_, v3 = s[f][3] * SCALE_;
                if (kt == by) {
                    if (c     > r0)     v0 = -1e30f;
                    if (c + 1 > r0)     v1 = -1e30f;
                    if (c     > r0 + 8) v2 = -1e30f;
                    if (c + 1 > r0 + 8) v3 = -1e30f;
                }
                Ps[r0 * FPS_LD + c] = v0;       Ps[r0 * FPS_LD + c + 1] = v1;
                Ps[(r0 + 8) * FPS_LD + c] = v2; Ps[(r0 + 8) * FPS_LD + c + 1] = v3;
            }
        }
        __syncthreads();

        // ---- online softmax: 4 threads per row, 16 cols each ----
        {
            int row = tid >> 2, sub = tid & 3;
            float* pr = Ps + row * FPS_LD + sub * 16;
            float mx = -1e30f;
            #pragma unroll
            for (int i = 0; i < 16; i++) mx = fmaxf(mx, pr[i]);
            mx = fmaxf(mx, __shfl_xor_sync(0xffffffffu, mx, 1));
            mx = fmaxf(mx, __shfl_xor_sync(0xffffffffu, mx, 2));
            float mold = m_s[row];
            float lold = l_s[row];
            float mnew = fmaxf(mold, mx);
            float fac = __expf(mold - mnew);
            float sum = 0.f;
            #pragma unroll
            for (int i = 0; i < 16; i++) {
                float p = __expf(pr[i] - mnew);
                pr[i] = p; sum += p;
            }
            sum += __shfl_xor_sync(0xffffffffu, sum, 1);
            sum += __shfl_xor_sync(0xffffffffu, sum, 2);
            m_s[row] = mnew;
            l_s[row] = lold * fac + sum;
            fac_s[row] = fac;
        }
        __syncthreads();

        // rescale O
        {
            float f0 = fac_s[wm * 16 + gid], f1 = fac_s[wm * 16 + gid + 8];
            #pragma unroll
            for (int f = 0; f < 8; f++) {
                o[f][0] *= f0; o[f][1] *= f0; o[f][2] *= f1; o[f][3] *= f1;
            }
        }

        // ---- O += P V (tf32 mma), warp tile m16 x n64 ----
        #pragma unroll
        for (int ks = 0; ks < 64; ks += 8) {
            unsigned a[4];
            int r0 = wm * 16 + gid;
            a[0] = __float_as_uint(Ps[r0 * FPS_LD + ks + tq]);
            a[1] = __float_as_uint(Ps[(r0 + 8) * FPS_LD + ks + tq]);
            a[2] = __float_as_uint(Ps[r0 * FPS_LD + ks + tq + 4]);
            a[3] = __float_as_uint(Ps[(r0 + 8) * FPS_LD + ks + tq + 4]);
            #pragma unroll
            for (int f = 0; f < 8; f++) {
                unsigned b[2];
                int c = wn * 64 + f * 8 + gid;
                b[0] = __float_as_uint(V[(ks + tq) * FKV_LD + c]);
                b[1] = __float_as_uint(V[(ks + tq + 4) * FKV_LD + c]);
                mma_tf32(o[f], a, b);
            }
        }
        (void)s0;
    }

    // epilogue
    {
        float inv0 = 1.f / l_s[wm * 16 + gid];
        float inv1 = 1.f / l_s[wm * 16 + gid + 8];
        int r0 = m0 + wm * 16 + gid;
        int r1 = r0 + 8;
        #pragma unroll
        for (int f = 0; f < 8; f++) {
            int c = wn * 64 + f * 8 + 2 * tq;
            float* d0 = &g_attnout[((size_t)r0 * NQ_ + n) * H_ + c];
            float* d1 = &g_attnout[((size_t)r1 * NQ_ + n) * H_ + c];
            d0[0] = o[f][0] * inv0; d0[1] = o[f][1] * inv0;
            d1[0] = o[f][2] * inv1; d1[1] = o[f][3] * inv1;
        }
    }
}

__global__ void __launch_bounds__(256) k_oproj(const float* __restrict__ W,
                                               const float* __restrict__ resid)
{
    extern __shared__ float dsm[];
    gemm_tf32_body(dsm, g_attnout, NQ_ * H_, W, D_, g_hres, D_,
                   blockIdx.x * 128, NQ_ * H_, resid, T_);
}

__global__ void k_zero()
{
    if (threadIdx.x < E_) g_counts[threadIdx.x] = 0;
}

__global__ void k_router(const float* __restrict__ gate_w)
{
    const int t = blockIdx.x, tid = threadIdx.x; // 128 threads
    const float* x = g_h2 + (size_t)t * D_;
    float acc[E_];
    #pragma unroll
    for (int e = 0; e < E_; e++) acc[e] = 0.f;
    for (int d = tid; d < D_; d += 128) {
        float xv = x[d];
        const float* gw = gate_w + (size_t)d * E_;
        #pragma unroll
        for (int e = 0; e < E_; e++) acc[e] = fmaf(xv, gw[e], acc[e]);
    }
    __shared__ float sh[128 * E_];
    #pragma unroll
    for (int e = 0; e < E_; e++) sh[tid * E_ + e] = acc[e];
    __syncthreads();
    for (int s = 64; s > 0; s >>= 1) {
        if (tid < s)
            #pragma unroll
            for (int e = 0; e < E_; e++) sh[tid * E_ + e] += sh[(tid + s) * E_ + e];
        __syncthreads();
    }
    if (tid == 0) {
        float p[E_];
        float m = -1e30f;
        for (int e = 0; e < E_; e++) m = fmaxf(m, sh[e]);
        float sum = 0.f;
        for (int e = 0; e < E_; e++) { p[e] = __expf(sh[e] - m); sum += p[e]; }
        float invs = 1.f / sum;
        for (int e = 0; e < E_; e++) p[e] *= invs;
        int idx[TOPK_]; float wv[TOPK_]; float wsum = 0.f;
        for (int k = 0; k < TOPK_; k++) {
            int best = 0; float bv = p[0];
            for (int e = 1; e < E_; e++) if (p[e] > bv) { bv = p[e]; best = e; }
            idx[k] = best; wv[k] = bv; wsum += bv; p[best] = -1.f;
        }
        float invw = 1.f / wsum;
        for (int k = 0; k < TOPK_; k++) {
            g_topidx[t * TOPK_ + k] = idx[k];
            g_topw[t * TOPK_ + k] = wv[k] * invw;
            atomicAdd(&g_counts[idx[k]], 1);
        }
    }
}

__global__ void k_scan()
{
    int off = 0;
    for (int e = 0; e < E_; e++) {
        g_offsets[e] = off;
        off += g_counts[e];
        g_cursor[e] = 0;
    }
}

__global__ void k_assign()
{
    int i = blockIdx.x * blockDim.x + threadIdx.x;
    if (i >= T_ * TOPK_) return;
    int e = g_topidx[i];
    int slot = g_offsets[e] + atomicAdd(&g_cursor[e], 1);
    g_pair_token[slot] = i >> 2;
    g_pair_slot[i] = slot;
}

// ---------------- MoE gate_up (tf32 mma, dual-B, SiLU, 3-stage cp.async) --------
#define BGU_LD 72
#define GU_SMEM ((3 * 128 * AS_LD + 2 * 3 * 16 * BGU_LD) * 4)
__global__ void __launch_bounds__(256) k_gateup(const float* __restrict__ gate_up_w)
{
    extern __shared__ float dsm[];
    float* As = dsm;                                 // [3][128][AS_LD]
    float* Bg = dsm + 3 * 128 * AS_LD;               // [3][16][BGU_LD]
    float* Bu = Bg + 3 * 16 * BGU_LD;                // [3][16][BGU_LD]
    __shared__ int rowTok[128];

    const int e = blockIdx.z;
    const int cnt = g_counts[e];
    const int m0 = blockIdx.y * 128;
    if (m0 >= cnt) return;
    const int base = g_offsets[e];
    const int n0 = blockIdx.x * 64;
    const float* B = gate_up_w + (size_t)e * D_ * (2 * F_);

    const int tid = threadIdx.x, lane = tid & 31, warp = tid >> 5;
    const int wm = warp >> 2, wn = warp & 3;
    const int gid = lane >> 2, tq = lane & 3;

    if (tid < 128) {
        int r = m0 + tid;
        rowTok[tid] = (r < cnt) ? g_pair_token[base + r] : g_pair_token[base];
    }
    __syncthreads();

    const int ar0 = tid >> 1;
    const int ac0 = (tid & 1) * 8;
    const size_t arow = (size_t)rowTok[ar0] * D_;
    const int br0 = tid >> 4;          // 0..15
    const int bc0 = (tid & 15) * 4;    // 0..60

    float ag[4][2][4] = {}, au[4][2][4] = {};

    const int niter = D_ >> 4;
    auto issue = [&](int it) {
        int k0 = it << 4;
        int st = it % 3;
        float* as = As + st * 128 * AS_LD;
        float* bgp = Bg + st * 16 * BGU_LD;
        float* bup = Bu + st * 16 * BGU_LD;
        cpa16(&as[ar0 * AS_LD + ac0],     &g_h2[arow + k0 + ac0]);
        cpa16(&as[ar0 * AS_LD + ac0 + 4], &g_h2[arow + k0 + ac0 + 4]);
        const float* brow = B + (size_t)(k0 + br0) * (2 * F_);
        cpa16(&bgp[br0 * BGU_LD + bc0], &brow[n0 + bc0]);
        cpa16(&bup[br0 * BGU_LD + bc0], &brow[F_ + n0 + bc0]);
        cpa_commit();
    };
    issue(0);
    issue(1);

    for (int it = 0; it < niter; it++) {
        if (it + 1 < niter) cpa_wait1(); else cpa_wait0();
        __syncthreads();
        if (it + 2 < niter) issue(it + 2);
        const float* as = As + (it % 3) * 128 * AS_LD;
        const float* bgp = Bg + (it % 3) * 16 * BGU_LD;
        const float* bup = Bu + (it % 3) * 16 * BGU_LD;
        #pragma unroll
        for (int ks = 0; ks < 16; ks += 8) {
            unsigned a[4][4], bg[2][2], bu[2][2];
            #pragma unroll
            for (int tm = 0; tm < 4; tm++) {
                int r0 = wm * 64 + tm * 16 + gid;
                a[tm][0] = __float_as_uint(as[r0 * AS_LD + ks + tq]);
                a[tm][1] = __float_as_uint(as[(r0 + 8) * AS_LD + ks + tq]);
                a[tm][2] = __float_as_uint(as[r0 * AS_LD + ks + tq + 4]);
                a[tm][3] = __float_as_uint(as[(r0 + 8) * AS_LD + ks + tq + 4]);
            }
            #pragma unroll
            for (int tn = 0; tn < 2; tn++) {
                int c = wn * 16 + tn * 8 + gid;
                bg[tn][0] = __float_as_uint(bgp[(ks + tq) * BGU_LD + c]);
                bg[tn][1] = __float_as_uint(bgp[(ks + tq + 4) * BGU_LD + c]);
                bu[tn][0] = __float_as_uint(bup[(ks + tq) * BGU_LD + c]);
                bu[tn][1] = __float_as_uint(bup[(ks + tq + 4) * BGU_LD + c]);
            }
            #pragma unroll
            for (int tm = 0; tm < 4; tm++)
                #pragma unroll
                for (int tn = 0; tn < 2; tn++) {
                    mma_tf32(ag[tm][tn], a[tm], bg[tn]);
                    mma_tf32(au[tm][tn], a[tm], bu[tn]);
                }
        }
        __syncthreads();
    }
    #pragma unroll
    for (int tm = 0; tm < 4; tm++) {
        int r0 = m0 + wm * 64 + tm * 16 + gid;
        int r1 = r0 + 8;
        #pragma unroll
        for (int tn = 0; tn < 2; tn++) {
            int c0 = n0 + wn * 16 + tn * 8 + 2 * tq;
            if (r0 < cnt) {
                float g0 = ag[tm][tn][0], u0 = au[tm][tn][0];
                float g1 = ag[tm][tn][1], u1 = au[tm][tn][1];
                g_gated[(size_t)(base + r0) * F_ + c0]     = u0 * (g0 / (1.f + __expf(-g0)));
                g_gated[(size_t)(base + r0) * F_ + c0 + 1] = u1 * (g1 / (1.f + __expf(-g1)));
            }
            if (r1 < cnt) {
                float g2 = ag[tm][tn][2], u2 = au[tm][tn][2];
                float g3 = ag[tm][tn][3], u3 = au[tm][tn][3];
                g_gated[(size_t)(base + r1) * F_ + c0]     = u2 * (g2 / (1.f + __expf(-g2)));
                g_gated[(size_t)(base + r1) * F_ + c0 + 1] = u3 * (g3 / (1.f + __expf(-g3)));
            }
        }
    }
}

__global__ void __launch_bounds__(256) k_down(const float* __restrict__ down_w)
{
    extern __shared__ float dsm[];
    const int e = blockIdx.z;
    const int cnt = g_counts[e];
    if ((int)blockIdx.y * 128 >= cnt) return;
    const int base = g_offsets[e];
    gemm_tf32_body(dsm, g_gated + (size_t)base * F_, F_,
                   down_w + (size_t)e * F_ * D_, D_,
                   g_pairout + (size_t)base * D_, D_,
                   blockIdx.x * 128, F_, nullptr, cnt);
}

__global__ void k_combine(float* __restrict__ out)
{
    const int t = blockIdx.x;
    const int s0 = g_pair_slot[t * 4 + 0], s1 = g_pair_slot[t * 4 + 1];
    const int s2 = g_pair_slot[t * 4 + 2], s3 = g_pair_slot[t * 4 + 3];
    const float w0 = g_topw[t * 4 + 0], w1 = g_topw[t * 4 + 1];
    const float w2 = g_topw[t * 4 + 2], w3 = g_topw[t * 4 + 3];
    const float* p0 = g_pairout + (size_t)s0 * D_;
    const float* p1 = g_pairout + (size_t)s1 * D_;
    const float* p2 = g_pairout + (size_t)s2 * D_;
    const float* p3 = g_pairout + (size_t)s3 * D_;
    const float* hr = g_hres + (size_t)t * D_;
    float* o = out + (size_t)t * D_;
    for (int d = threadIdx.x; d < D_; d += 256)
        o[d] = hr[d] + w0 * p0[d] + w1 * p1[d] + w2 * p2[d] + w3 * p3[d];
}

// ---------------- launch ----------------
extern "C" void kernel_launch(void* const* d_in, const int* in_sizes, int n_in,
                              void* d_out, int out_size)
{
    const float* hidden = (const float*)d_in[0];
    const float* cosp   = (const float*)d_in[1];
    const float* sinp   = (const float*)d_in[2];
    const float* iln    = (const float*)d_in[4];
    const float* pln    = (const float*)d_in[5];
    const float* qw     = (const float*)d_in[6];
    const float* kw     = (const float*)d_in[7];
    const float* vw     = (const float*)d_in[8];
    const float* ow     = (const float*)d_in[9];
    const float* qnw    = (const float*)d_in[10];
    const float* knw    = (const float*)d_in[11];
    const float* gw     = (const float*)d_in[12];
    const float* guw    = (const float*)d_in[13];
    const float* dw     = (const float*)d_in[14];
    float* out = (float*)d_out;

    static bool attr_set = false;
    if (!attr_set) {
        cudaFuncSetAttribute(k_flashattn, cudaFuncAttributeMaxDynamicSharedMemorySize, FA_SMEM);
        cudaFuncSetAttribute(k_qkv,    cudaFuncAttributeMaxDynamicSharedMemorySize, GEMM_SMEM);
        cudaFuncSetAttribute(k_oproj,  cudaFuncAttributeMaxDynamicSharedMemorySize, GEMM_SMEM);
        cudaFuncSetAttribute(k_down,   cudaFuncAttributeMaxDynamicSharedMemorySize, GEMM_SMEM);
        cudaFuncSetAttribute(k_gateup, cudaFuncAttributeMaxDynamicSharedMemorySize, GU_SMEM);
        attr_set = true;
    }

    k_rmsnorm<<<T_, 256>>>(hidden, iln, 0);
    k_qkv<<<dim3(24, T_ / 128), 256, GEMM_SMEM>>>(qw, kw, vw);
    k_normrope<<<dim3(T_, NQ_), 128>>>(qnw, cosp, sinp, 0);
    k_normrope<<<dim3(T_, NKV_), 128>>>(knw, cosp, sinp, 1);
    k_flashattn<<<dim3(T_ / 64, NQ_), 256, FA_SMEM>>>();
    k_oproj<<<dim3(D_ / 128, T_ / 128), 256, GEMM_SMEM>>>(ow, hidden);
    k_rmsnorm<<<T_, 256>>>(nullptr, pln, 1);
    k_zero<<<1, 32>>>();
    k_router<<<T_, 128>>>(gw);
    k_scan<<<1, 1>>>();
    k_assign<<<(T_ * TOPK_ + 255) / 256, 256>>>();
    k_gateup<<<dim3(F_ / 64, T_ * TOPK_ / 128, E_), 256, GU_SMEM>>>(guw);
    k_down<<<dim3(D_ / 128, T_ * TOPK_ / 128, E_), 256, GEMM_SMEM>>>(dw);
    k_combine<<<T_, 256>>>(out);
}